// round 13
// baseline (speedup 1.0000x reference)
#include <cuda_runtime.h>
#include <cuda_bf16.h>
#include <cuda_fp16.h>
#include <cstdint>

#define D_MODEL 1024
#define NH      16
#define HS      64
#define BATCH   2
#define SEQ     2048
#define MROWS   (BATCH*SEQ)   // 4096
#define ACT_N   ((size_t)MROWS*D_MODEL)   // 4M
#define W_N     ((size_t)D_MODEL*D_MODEL) // 1M
#define MWORDS  ((size_t)BATCH*NH*SEQ*SEQ/32)  // 4,194,304
#define QSCALE  0.18033688011112042f   // 0.125 * log2(e)

// ---------------- scratch (no allocations allowed) ----------------
__device__ __nv_bfloat16 g_xh[3][ACT_N], g_xl[3][ACT_N];  // preconverted activations
__device__ __nv_bfloat16 g_wh[4][W_N],  g_wl[4][W_N];     // preconverted weights
__device__ __half g_qkvf[3][ACT_N];   // q/k/v head-split [B,H,S,HS] fp16 (q pre-scaled)
__device__ __nv_bfloat16 g_oh[ACT_N], g_ol[ACT_N];        // attn out split-bf16, merged
__device__ uint32_t g_mbits[MWORDS];

// ---------------- helpers ----------------
__device__ __forceinline__ uint32_t smem_u32(const void* p) {
    return (uint32_t)__cvta_generic_to_shared(p);
}
__device__ __forceinline__ void ldm_x4(uint32_t& r0, uint32_t& r1, uint32_t& r2, uint32_t& r3,
                                       uint32_t addr) {
    asm volatile("ldmatrix.sync.aligned.m8n8.x4.shared.b16 {%0,%1,%2,%3}, [%4];\n"
                 : "=r"(r0), "=r"(r1), "=r"(r2), "=r"(r3) : "r"(addr));
}
__device__ __forceinline__ void ldm_x4_trans(uint32_t& r0, uint32_t& r1, uint32_t& r2, uint32_t& r3,
                                             uint32_t addr) {
    asm volatile("ldmatrix.sync.aligned.m8n8.x4.trans.shared.b16 {%0,%1,%2,%3}, [%4];\n"
                 : "=r"(r0), "=r"(r1), "=r"(r2), "=r"(r3) : "r"(addr));
}
__device__ __forceinline__ void mma_bf16(float* c, const uint32_t* a, const uint32_t* b) {
    asm volatile("mma.sync.aligned.m16n8k16.row.col.f32.bf16.bf16.f32 "
                 "{%0,%1,%2,%3}, {%4,%5,%6,%7}, {%8,%9}, {%0,%1,%2,%3};\n"
                 : "+f"(c[0]), "+f"(c[1]), "+f"(c[2]), "+f"(c[3])
                 : "r"(a[0]), "r"(a[1]), "r"(a[2]), "r"(a[3]), "r"(b[0]), "r"(b[1]));
}
__device__ __forceinline__ void mma_f16(float* c, const uint32_t* a, const uint32_t* b) {
    asm volatile("mma.sync.aligned.m16n8k16.row.col.f32.f16.f16.f32 "
                 "{%0,%1,%2,%3}, {%4,%5,%6,%7}, {%8,%9}, {%0,%1,%2,%3};\n"
                 : "+f"(c[0]), "+f"(c[1]), "+f"(c[2]), "+f"(c[3])
                 : "r"(a[0]), "r"(a[1]), "r"(a[2]), "r"(a[3]), "r"(b[0]), "r"(b[1]));
}
__device__ __forceinline__ void split2pack(float x0, float x1, uint32_t& h, uint32_t& l) {
    __nv_bfloat16 h0 = __float2bfloat16(x0), h1 = __float2bfloat16(x1);
    float r0 = x0 - __bfloat162float(h0);
    float r1 = x1 - __bfloat162float(h1);
    __nv_bfloat16 l0 = __float2bfloat16(r0), l1 = __float2bfloat16(r1);
    h = ((uint32_t)__bfloat16_as_ushort(h1) << 16) | (uint32_t)__bfloat16_as_ushort(h0);
    l = ((uint32_t)__bfloat16_as_ushort(l1) << 16) | (uint32_t)__bfloat16_as_ushort(l0);
}
__device__ __forceinline__ uint32_t packh2(float x0, float x1) {
    __half2 h = __floats2half2_rn(x0, x1);
    return *(uint32_t*)&h;
}
__device__ __forceinline__ uint32_t h2exp2(uint32_t x) {
    uint32_t r;
    asm("ex2.approx.f16x2 %0, %1;" : "=r"(r) : "r"(x));
    return r;
}
__device__ __forceinline__ uint32_t mask2(uint32_t w, int bp) {
    return (((w >> bp) & 1u) ? 0x0000FFFFu : 0u) |
           (((w >> (bp + 1)) & 1u) ? 0xFFFF0000u : 0u);
}
__device__ __forceinline__ void cp16(uint32_t dst, const void* src) {
    asm volatile("cp.async.cg.shared.global [%0], [%1], 16;\n" :: "r"(dst), "l"(src));
}
#define CP_COMMIT asm volatile("cp.async.commit_group;\n")
#define CP_WAIT0  asm volatile("cp.async.wait_group 0;\n" ::: "memory")
#define CP_WAIT1  asm volatile("cp.async.wait_group 1;\n" ::: "memory")

// ---------------- mask -> bitmask ----------------
__global__ void __launch_bounds__(256)
maskbits_kernel(const int* __restrict__ mask, uint32_t* __restrict__ bits)
{
    size_t widx = (size_t)blockIdx.x * 8 + (threadIdx.x >> 5);
    int lane = threadIdx.x & 31;
    int m = mask[widx * 32 + lane];
    uint32_t b = __ballot_sync(0xffffffff, m != 0);
    if (lane == 0) bits[widx] = b;
}

// ---------------- fused preconversion ----------------
__global__ void __launch_bounds__(256)
splitw4_kernel(const float* __restrict__ w0, const float* __restrict__ w1,
               const float* __restrict__ w2, const float* __restrict__ w3,
               __nv_bfloat16* __restrict__ hi, __nv_bfloat16* __restrict__ lo)
{
    const int y = blockIdx.y;
    const float* in = (y == 0) ? w0 : (y == 1) ? w1 : (y == 2) ? w2 : w3;
    size_t i = (size_t)blockIdx.x * 256 + threadIdx.x;
    float4 v = ((const float4*)in)[i];
    uint2 h, l;
    split2pack(v.x, v.y, h.x, l.x);
    split2pack(v.z, v.w, h.y, l.y);
    ((uint2*)(hi + y * W_N))[i] = h;
    ((uint2*)(lo + y * W_N))[i] = l;
}
__global__ void __launch_bounds__(256)
split_kernel(const float* __restrict__ in, __nv_bfloat16* __restrict__ hi,
             __nv_bfloat16* __restrict__ lo)
{
    size_t i = (size_t)blockIdx.x * 256 + threadIdx.x;
    float4 v = ((const float4*)in)[i];
    uint2 h, l;
    split2pack(v.x, v.y, h.x, l.x);
    split2pack(v.z, v.w, h.y, l.y);
    ((uint2*)hi)[i] = h;
    ((uint2*)lo)[i] = l;
}
__global__ void __launch_bounds__(256)
splita2_kernel(const float* __restrict__ a0, const float* __restrict__ a1,
               __nv_bfloat16* __restrict__ hi, __nv_bfloat16* __restrict__ lo)
{
    const int y = blockIdx.y;
    const float* in = y ? a1 : a0;
    size_t i = (size_t)blockIdx.x * 256 + threadIdx.x;
    float4 v = ((const float4*)in)[i];
    uint2 h, l;
    split2pack(v.x, v.y, h.x, l.x);
    split2pack(v.z, v.w, h.y, l.y);
    ((uint2*)(hi + (size_t)y * ACT_N))[i] = h;
    ((uint2*)(lo + (size_t)y * ACT_N))[i] = l;
}

// ================= Fused QKV GEMM (R11-proven) =================
#define GSTR 40   // 32 + 8 pad (bf16 elems)

struct QSmem {
    __nv_bfloat16 Ah[2][128][GSTR], Al[2][128][GSTR];
    __nv_bfloat16 Wh[2][128][GSTR], Wl[2][128][GSTR];
};  // 81920 B

__global__ void __launch_bounds__(256, 2)
qkv_gemm_kernel(const __nv_bfloat16* __restrict__ xh_g, const __nv_bfloat16* __restrict__ xl_g,
                const __nv_bfloat16* __restrict__ wh_g, const __nv_bfloat16* __restrict__ wl_g,
                const float* __restrict__ b1q, const float* __restrict__ b2q,
                const float* __restrict__ b1k, const float* __restrict__ b2k,
                const float* __restrict__ b1v, const float* __restrict__ b2v,
                __half* __restrict__ out_g)
{
    extern __shared__ char smem_raw[];
    QSmem* S = (QSmem*)smem_raw;

    const int wsel = blockIdx.x >> 3;
    const int m0 = blockIdx.y * 128, n0 = (blockIdx.x & 7) * 128;
    const int tid = threadIdx.x;
    const int w = tid >> 5, lane = tid & 31;
    const int wm = w & 1, wn = w >> 1;
    const int rm = wm * 64, rn = wn * 32;
    const int lr = lane & 15, lc = (lane >> 4) << 3;
    const int tig = lane & 3, gid = lane >> 2;

    const __nv_bfloat16* srcAh = xh_g + (size_t)wsel * ACT_N + (size_t)m0 * D_MODEL;
    const __nv_bfloat16* srcAl = xl_g + (size_t)wsel * ACT_N + (size_t)m0 * D_MODEL;
    const __nv_bfloat16* srcWh = wh_g + (size_t)wsel * W_N + (size_t)n0 * D_MODEL;
    const __nv_bfloat16* srcWl = wl_g + (size_t)wsel * W_N + (size_t)n0 * D_MODEL;
    const float* b1 = (wsel == 0) ? b1q : (wsel == 1) ? b1k : b1v;
    const float* b2 = (wsel == 0) ? b2q : (wsel == 1) ? b2k : b2v;
    const float scale = (wsel == 0) ? QSCALE : 1.f;
    __half* oH = out_g + (size_t)wsel * ACT_N;

    float cf[4][4][4];
    #pragma unroll
    for (int mi = 0; mi < 4; mi++)
        #pragma unroll
        for (int ni = 0; ni < 4; ni++)
            #pragma unroll
            for (int e = 0; e < 4; e++) cf[mi][ni][e] = 0.f;

    auto stage = [&](int kt, int buf) {
        const int kofs = kt * 32;
        #pragma unroll
        for (int i = 0; i < 8; i++) {
            int idx = tid + i * 256;
            int arr = idx >> 9;
            int rem = idx & 511;
            int r = rem >> 2, c = (rem & 3) << 3;
            const __nv_bfloat16* src =
                (arr == 0 ? srcAh : arr == 1 ? srcAl : arr == 2 ? srcWh : srcWl)
                + (size_t)r * D_MODEL + kofs + c;
            uint32_t dst = smem_u32(
                arr == 0 ? (void*)&S->Ah[buf][r][c] : arr == 1 ? (void*)&S->Al[buf][r][c] :
                arr == 2 ? (void*)&S->Wh[buf][r][c] : (void*)&S->Wl[buf][r][c]);
            cp16(dst, src);
        }
        CP_COMMIT;
    };

    stage(0, 0);
    stage(1, 1);

    const int NKT = D_MODEL / 32;
    for (int kt = 0; kt < NKT; kt++) {
        const int buf = kt & 1;
        if (kt + 1 < NKT) { CP_WAIT1; } else { CP_WAIT0; }
        __syncthreads();

        #pragma unroll
        for (int ks = 0; ks < 2; ks++) {
            const int kb = ks * 16;
            uint32_t ah[4][4], al[4][4];
            #pragma unroll
            for (int mi = 0; mi < 4; mi++) {
                ldm_x4(ah[mi][0], ah[mi][1], ah[mi][2], ah[mi][3],
                       smem_u32(&S->Ah[buf][rm + mi * 16 + lr][kb + lc]));
                ldm_x4(al[mi][0], al[mi][1], al[mi][2], al[mi][3],
                       smem_u32(&S->Al[buf][rm + mi * 16 + lr][kb + lc]));
            }
            uint32_t bh[4][2], bl[4][2];
            #pragma unroll
            for (int g = 0; g < 2; g++) {
                uint32_t r0, r1, r2, r3;
                ldm_x4(r0, r1, r2, r3, smem_u32(&S->Wh[buf][rn + g * 16 + lr][kb + lc]));
                bh[2*g][0] = r0; bh[2*g+1][0] = r1; bh[2*g][1] = r2; bh[2*g+1][1] = r3;
                ldm_x4(r0, r1, r2, r3, smem_u32(&S->Wl[buf][rn + g * 16 + lr][kb + lc]));
                bl[2*g][0] = r0; bl[2*g+1][0] = r1; bl[2*g][1] = r2; bl[2*g+1][1] = r3;
            }
            #pragma unroll
            for (int mi = 0; mi < 4; mi++)
                #pragma unroll
                for (int ni = 0; ni < 4; ni++) {
                    mma_bf16(cf[mi][ni], ah[mi], bh[ni]);
                    mma_bf16(cf[mi][ni], ah[mi], bl[ni]);
                    mma_bf16(cf[mi][ni], al[mi], bh[ni]);
                }
        }
        __syncthreads();
        if (kt + 2 < NKT) stage(kt + 2, buf);
    }

    #pragma unroll
    for (int ni = 0; ni < 4; ni++) {
        const int c0 = rn + ni * 8 + tig * 2 + n0;
        const float bias0 = b1[c0] + b2[c0];
        const float bias1 = b1[c0 + 1] + b2[c0 + 1];
        #pragma unroll
        for (int mi = 0; mi < 4; mi++) {
            #pragma unroll
            for (int half = 0; half < 2; half++) {
                int m = m0 + rm + mi * 16 + gid + half * 8;
                float v0 = (cf[mi][ni][half * 2]     + bias0) * scale;
                float v1 = (cf[mi][ni][half * 2 + 1] + bias1) * scale;
                int bb = m >> 11, s = m & (SEQ - 1);
                int hh = c0 >> 6, d = c0 & (HS - 1);
                size_t off = (((size_t)(bb * NH + hh)) * SEQ + s) * HS + d;
                *(uint32_t*)&oH[off] = packh2(v0, v1);
            }
        }
    }
}

// ================= Y GEMM: fully async (attn out split-bf16 @ Wy^T + bias) =================
__global__ void __launch_bounds__(256, 2)
y_gemm_kernel(const __nv_bfloat16* __restrict__ Ahg, const __nv_bfloat16* __restrict__ Alg,
              const __nv_bfloat16* __restrict__ Whg, const __nv_bfloat16* __restrict__ Wlg,
              const float* __restrict__ b1, const float* __restrict__ b2,
              float* __restrict__ outF)
{
    extern __shared__ char smem_raw[];
    QSmem* S = (QSmem*)smem_raw;

    const int m0 = blockIdx.y * 128, n0 = blockIdx.x * 128;
    const int tid = threadIdx.x;
    const int w = tid >> 5, lane = tid & 31;
    const int wm = w & 1, wn = w >> 1;
    const int rm = wm * 64, rn = wn * 32;
    const int lr = lane & 15, lc = (lane >> 4) << 3;
    const int tig = lane & 3, gid = lane >> 2;

    const __nv_bfloat16* srcAh = Ahg + (size_t)m0 * D_MODEL;
    const __nv_bfloat16* srcAl = Alg + (size_t)m0 * D_MODEL;
    const __nv_bfloat16* srcWh = Whg + (size_t)n0 * D_MODEL;
    const __nv_bfloat16* srcWl = Wlg + (size_t)n0 * D_MODEL;

    float cf[4][4][4];
    #pragma unroll
    for (int mi = 0; mi < 4; mi++)
        #pragma unroll
        for (int ni = 0; ni < 4; ni++)
            #pragma unroll
            for (int e = 0; e < 4; e++) cf[mi][ni][e] = 0.f;

    auto stage = [&](int kt, int buf) {
        const int kofs = kt * 32;
        #pragma unroll
        for (int i = 0; i < 8; i++) {
            int idx = tid + i * 256;
            int arr = idx >> 9;
            int rem = idx & 511;
            int r = rem >> 2, c = (rem & 3) << 3;
            const __nv_bfloat16* src =
                (arr == 0 ? srcAh : arr == 1 ? srcAl : arr == 2 ? srcWh : srcWl)
                + (size_t)r * D_MODEL + kofs + c;
            uint32_t dst = smem_u32(
                arr == 0 ? (void*)&S->Ah[buf][r][c] : arr == 1 ? (void*)&S->Al[buf][r][c] :
                arr == 2 ? (void*)&S->Wh[buf][r][c] : (void*)&S->Wl[buf][r][c]);
            cp16(dst, src);
        }
        CP_COMMIT;
    };

    stage(0, 0);
    stage(1, 1);

    const int NKT = D_MODEL / 32;
    for (int kt = 0; kt < NKT; kt++) {
        const int buf = kt & 1;
        if (kt + 1 < NKT) { CP_WAIT1; } else { CP_WAIT0; }
        __syncthreads();

        #pragma unroll
        for (int ks = 0; ks < 2; ks++) {
            const int kb = ks * 16;
            uint32_t ah[4][4], al[4][4];
            #pragma unroll
            for (int mi = 0; mi < 4; mi++) {
                ldm_x4(ah[mi][0], ah[mi][1], ah[mi][2], ah[mi][3],
                       smem_u32(&S->Ah[buf][rm + mi * 16 + lr][kb + lc]));
                ldm_x4(al[mi][0], al[mi][1], al[mi][2], al[mi][3],
                       smem_u32(&S->Al[buf][rm + mi * 16 + lr][kb + lc]));
            }
            uint32_t bh[4][2], bl[4][2];
            #pragma unroll
            for (int g = 0; g < 2; g++) {
                uint32_t r0, r1, r2, r3;
                ldm_x4(r0, r1, r2, r3, smem_u32(&S->Wh[buf][rn + g * 16 + lr][kb + lc]));
                bh[2*g][0] = r0; bh[2*g+1][0] = r1; bh[2*g][1] = r2; bh[2*g+1][1] = r3;
                ldm_x4(r0, r1, r2, r3, smem_u32(&S->Wl[buf][rn + g * 16 + lr][kb + lc]));
                bl[2*g][0] = r0; bl[2*g+1][0] = r1; bl[2*g][1] = r2; bl[2*g+1][1] = r3;
            }
            #pragma unroll
            for (int mi = 0; mi < 4; mi++)
                #pragma unroll
                for (int ni = 0; ni < 4; ni++) {
                    mma_bf16(cf[mi][ni], ah[mi], bh[ni]);
                    mma_bf16(cf[mi][ni], ah[mi], bl[ni]);
                    mma_bf16(cf[mi][ni], al[mi], bh[ni]);
                }
        }
        __syncthreads();
        if (kt + 2 < NKT) stage(kt + 2, buf);
    }

    #pragma unroll
    for (int ni = 0; ni < 4; ni++) {
        const int c0 = n0 + rn + ni * 8 + tig * 2;
        const float bias0 = b1[c0] + b2[c0];
        const float bias1 = b1[c0 + 1] + b2[c0 + 1];
        #pragma unroll
        for (int mi = 0; mi < 4; mi++) {
            #pragma unroll
            for (int half = 0; half < 2; half++) {
                int m = m0 + rm + mi * 16 + gid + half * 8;
                *(float2*)&outF[(size_t)m * D_MODEL + c0] =
                    make_float2(cf[mi][ni][half * 2] + bias0, cf[mi][ni][half * 2 + 1] + bias1);
            }
        }
    }
}

// ================= Attention (R12-proven): 256 thr, 2 CTAs/SM =================
#define AT_SMEM (3*2*64*72*2)   // 55296 B

__global__ void __launch_bounds__(256, 2)
attn_kernel(const __half* __restrict__ qkv_g, const uint32_t* __restrict__ mbits,
            __nv_bfloat16* __restrict__ oh_g, __nv_bfloat16* __restrict__ ol_g)
{
    extern __shared__ char smem_raw[];
    typedef __half KVbuf[2][64][72];
    KVbuf* KV = (KVbuf*)smem_raw;

    const int tid = threadIdx.x;
    const int h = blockIdx.y, b = blockIdx.z;
    const int bh = b * NH + h;
    const int q0 = blockIdx.x * 128;
    const int w = tid >> 5, lane = tid & 31;
    const int lr = lane & 15, lc = (lane >> 4) << 3;
    const int tig = lane & 3, gid = lane >> 2;
    const int vr = ((lane >> 4) << 3) + (lane & 7), vc = lane & 8;

    const __half* qf_g = qkv_g;
    const __half* kf_g = qkv_g + ACT_N;
    const __half* vf_g = qkv_g + 2 * ACT_N;
    const size_t kvbase = (size_t)bh * SEQ * HS;

    {
        __half (*Qs)[72] = (__half (*)[72])&KV[0][0][0][0];
        #pragma unroll
        for (int j = 0; j < 4; j++) {
            int idx = tid + j * 256;
            int r = idx >> 3, c = (idx & 7) << 3;
            cp16(smem_u32(&Qs[r][c]), qf_g + kvbase + (size_t)(q0 + r) * HS + c);
        }
        CP_COMMIT; CP_WAIT0;
        __syncthreads();
    }
    uint32_t qf[4][4];
    {
        __half (*Qs)[72] = (__half (*)[72])&KV[0][0][0][0];
        #pragma unroll
        for (int ks = 0; ks < 4; ks++)
            ldm_x4(qf[ks][0], qf[ks][1], qf[ks][2], qf[ks][3],
                   smem_u32(&Qs[w * 16 + lr][ks * 16 + lc]));
        __syncthreads();
    }

    float oacc[8][4];
    #pragma unroll
    for (int nt = 0; nt < 8; nt++)
        #pragma unroll
        for (int e = 0; e < 4; e++) oacc[nt][e] = 0.f;
    float rsacc[4] = {0.f, 0.f, 0.f, 0.f};

    const uint32_t* mrow0 = mbits + ((size_t)(bh * SEQ) + q0 + w * 16 + gid) * 64;
    const uint32_t* mrow1 = mrow0 + 8 * 64;

    auto stage_kv = [&](int t, int buf) {
        #pragma unroll
        for (int j = 0; j < 4; j++) {
            int idx = tid + j * 256;
            int a = idx >> 9, rem = idx & 511;
            int r = rem >> 3, c = (rem & 7) << 3;
            const __half* src = (a ? vf_g : kf_g) + kvbase + (size_t)(t * 64 + r) * HS + c;
            cp16(smem_u32(&KV[buf][a][r][c]), src);
        }
        CP_COMMIT;
    };

    stage_kv(0, 0);
    stage_kv(1, 1);

    const uint32_t vones[2] = {0x3C003C00u, 0x3C003C00u};
    const int NT = SEQ / 64;

    uint32_t mw0a = mrow0[0], mw0b = mrow0[1];
    uint32_t mw1a = mrow1[0], mw1b = mrow1[1];

    for (int t = 0; t < NT; t++) {
        const int buf = t % 3;
        if (t + 1 < NT) { CP_WAIT1; } else { CP_WAIT0; }
        __syncthreads();
        if (t + 2 < NT) stage_kv(t + 2, (t + 2) % 3);

        uint32_t n0a = 0, n0b = 0, n1a = 0, n1b = 0;
        if (t + 1 < NT) {
            n0a = mrow0[(t + 1) * 2]; n0b = mrow0[(t + 1) * 2 + 1];
            n1a = mrow1[(t + 1) * 2]; n1b = mrow1[(t + 1) * 2 + 1];
        }

        const __half (*Kf)[72] = KV[buf][0];
        const __half (*Vf)[72] = KV[buf][1];

        float sc[8][4];
        #pragma unroll
        for (int nt = 0; nt < 8; nt++)
            #pragma unroll
            for (int e = 0; e < 4; e++) sc[nt][e] = 0.f;

        #pragma unroll
        for (int ks = 0; ks < 4; ks++) {
            const int kb = ks * 16;
            uint32_t kf[8][2];
            #pragma unroll
            for (int g = 0; g < 4; g++) {
                uint32_t r0, r1, r2, r3;
                ldm_x4(r0, r1, r2, r3, smem_u32(&Kf[g * 16 + lr][kb + lc]));
                kf[2*g][0] = r0; kf[2*g+1][0] = r1; kf[2*g][1] = r2; kf[2*g+1][1] = r3;
            }
            #pragma unroll
            for (int nt = 0; nt < 8; nt++)
                mma_f16(sc[nt], qf[ks], kf[nt]);
        }

        uint32_t pf[4][4];
        #pragma unroll
        for (int nt = 0; nt < 8; nt++) {
            const uint32_t w0 = (nt < 4) ? mw0a : mw0b;
            const uint32_t w1 = (nt < 4) ? mw1a : mw1b;
            const int bp = (nt & 3) * 8 + tig * 2;
            uint32_t e01 = h2exp2(packh2(sc[nt][0], sc[nt][1])) & mask2(w0, bp);
            uint32_t e23 = h2exp2(packh2(sc[nt][2], sc[nt][3])) & mask2(w1, bp);
            pf[nt >> 1][(nt & 1) * 2]     = e01;
            pf[nt >> 1][(nt & 1) * 2 + 1] = e23;
        }

        #pragma unroll
        for (int kp = 0; kp < 4; kp++) {
            mma_f16(rsacc, pf[kp], vones);
            const int krow = kp * 16 + vr;
            #pragma unroll
            for (int g = 0; g < 4; g++) {
                uint32_t vf[2][2];
                uint32_t r0, r1, r2, r3;
                ldm_x4_trans(r0, r1, r2, r3, smem_u32(&Vf[krow][g * 16 + vc]));
                vf[0][0] = r0; vf[1][0] = r1; vf[0][1] = r2; vf[1][1] = r3;
                mma_f16(oacc[2*g + 0], pf[kp], vf[0]);
                mma_f16(oacc[2*g + 1], pf[kp], vf[1]);
            }
        }
        mw0a = n0a; mw0b = n0b; mw1a = n1a; mw1b = n1b;
    }

    const float inv0 = 1.f / rsacc[0], inv1 = 1.f / rsacc[2];
    const size_t orow0 = (size_t)(b * SEQ + q0 + w * 16 + gid) * D_MODEL + h * HS;
    const size_t orow1 = orow0 + 8 * D_MODEL;
    #pragma unroll
    for (int nt = 0; nt < 8; nt++) {
        const int c = nt * 8 + tig * 2;
        uint32_t hh, ll;
        split2pack(oacc[nt][0] * inv0, oacc[nt][1] * inv0, hh, ll);
        *(uint32_t*)&oh_g[orow0 + c] = hh;
        *(uint32_t*)&ol_g[orow0 + c] = ll;
        split2pack(oacc[nt][2] * inv1, oacc[nt][3] * inv1, hh, ll);
        *(uint32_t*)&oh_g[orow1 + c] = hh;
        *(uint32_t*)&ol_g[orow1 + c] = ll;
    }
}

// ---------------- launch ----------------
extern "C" void kernel_launch(void* const* d_in, const int* in_sizes, int n_in,
                              void* d_out, int out_size)
{
    const float* queries = (const float*)d_in[0];
    const float* keys    = (const float*)d_in[1];
    const float* values  = (const float*)d_in[2];
    const int*   mask    = (const int*)d_in[3];
    const float* Wq = (const float*)d_in[4];  const float* bq = (const float*)d_in[5];
    const float* Wk = (const float*)d_in[6];  const float* bk = (const float*)d_in[7];
    const float* Wv = (const float*)d_in[8];  const float* bv = (const float*)d_in[9];
    const float* Wy = (const float*)d_in[10]; const float* by = (const float*)d_in[11];
    const float* bq2 = (const float*)d_in[12];
    const float* bk2 = (const float*)d_in[13];
    const float* bv2 = (const float*)d_in[14];
    const float* by2 = (const float*)d_in[15];
    float* out = (float*)d_out;

    __nv_bfloat16 *xh, *xl, *wh, *wl, *oh, *ol;
    __half* qkvf;
    uint32_t* mb;
    cudaGetSymbolAddress((void**)&xh, g_xh);   cudaGetSymbolAddress((void**)&xl, g_xl);
    cudaGetSymbolAddress((void**)&wh, g_wh);   cudaGetSymbolAddress((void**)&wl, g_wl);
    cudaGetSymbolAddress((void**)&oh, g_oh);   cudaGetSymbolAddress((void**)&ol, g_ol);
    cudaGetSymbolAddress((void**)&qkvf, g_qkvf);
    cudaGetSymbolAddress((void**)&mb, g_mbits);

    static int attr_set = 0;
    static cudaStream_t s2 = nullptr;
    static cudaEvent_t evFork = nullptr, evJoin = nullptr;
    if (!attr_set) {
        cudaFuncSetAttribute(qkv_gemm_kernel, cudaFuncAttributeMaxDynamicSharedMemorySize,
                             (int)sizeof(QSmem));
        cudaFuncSetAttribute(y_gemm_kernel, cudaFuncAttributeMaxDynamicSharedMemorySize,
                             (int)sizeof(QSmem));
        cudaFuncSetAttribute(attn_kernel, cudaFuncAttributeMaxDynamicSharedMemorySize,
                             AT_SMEM);
        // created on the (uncaptured) correctness call; reused under capture
        if (cudaStreamCreateWithFlags(&s2, cudaStreamNonBlocking) != cudaSuccess) s2 = nullptr;
        if (s2) {
            if (cudaEventCreateWithFlags(&evFork, cudaEventDisableTiming) != cudaSuccess ||
                cudaEventCreateWithFlags(&evJoin, cudaEventDisableTiming) != cudaSuccess) {
                s2 = nullptr;
            }
        }
        attr_set = 1;
    }

    const int W4 = (int)(W_N / 4), A4 = (int)(ACT_N / 4);
    const bool fork = (s2 != nullptr);

    // ---- fork: mask bitpack (512MB read, DRAM-bound) overlaps the QKV pipeline ----
    if (fork) {
        cudaEventRecord(evFork, 0);
        cudaStreamWaitEvent(s2, evFork, 0);
        maskbits_kernel<<<(int)(MWORDS / 8), 256, 0, s2>>>(mask, mb);
        cudaEventRecord(evJoin, s2);
    } else {
        maskbits_kernel<<<(int)(MWORDS / 8), 256>>>(mask, mb);
    }

    // ---- main stream: preconversion + fused QKV GEMM (tensor-bound) ----
    splitw4_kernel<<<dim3(W4 / 256, 4), 256>>>(Wq, Wk, Wv, Wy, wh, wl);
    split_kernel<<<A4 / 256, 256>>>(queries, xh, xl);
    splita2_kernel<<<dim3(A4 / 256, 2), 256>>>(keys, values, xh + ACT_N, xl + ACT_N);

    dim3 qgrid(24, MROWS / 128);
    qkv_gemm_kernel<<<qgrid, 256, sizeof(QSmem)>>>(xh, xl, wh, wl,
                                                   bq, bq2, bk, bk2, bv, bv2, qkvf);

    // ---- join before attention (needs mask bits) ----
    if (fork) cudaStreamWaitEvent(0, evJoin, 0);

    dim3 agrid(SEQ / 128, NH, BATCH);
    attn_kernel<<<agrid, 256, AT_SMEM>>>(qkvf, mb, oh, ol);

    dim3 ygrid(D_MODEL / 128, MROWS / 128);
    y_gemm_kernel<<<ygrid, 256, sizeof(QSmem)>>>(oh, ol, wh + 3 * W_N, wl + 3 * W_N,
                                                 by, by2, out);
}

// round 14
// speedup vs baseline: 1.1172x; 1.1172x over previous
#include <cuda_runtime.h>
#include <cuda_bf16.h>
#include <cuda_fp16.h>
#include <cstdint>

#define D_MODEL 1024
#define NH      16
#define HS      64
#define BATCH   2
#define SEQ     2048
#define MROWS   (BATCH*SEQ)   // 4096
#define ACT_N   ((size_t)MROWS*D_MODEL)   // 4M
#define W_N     ((size_t)D_MODEL*D_MODEL) // 1M
#define MWORDS  ((size_t)BATCH*NH*SEQ*SEQ/32)  // 4,194,304
#define QSCALE  0.18033688011112042f   // 0.125 * log2(e)

// ---------------- scratch (no allocations allowed) ----------------
__device__ __nv_bfloat16 g_xh[3][ACT_N], g_xl[3][ACT_N];  // preconverted activations
__device__ __nv_bfloat16 g_wh[4][W_N],  g_wl[4][W_N];     // preconverted weights
__device__ __half g_qkvf[3][ACT_N];   // q/k/v head-split [B,H,S,HS] fp16 (q pre-scaled)
__device__ __nv_bfloat16 g_oh[ACT_N], g_ol[ACT_N];        // attn out split-bf16, merged
__device__ uint32_t g_mbits[MWORDS];

// ---------------- helpers ----------------
__device__ __forceinline__ uint32_t smem_u32(const void* p) {
    return (uint32_t)__cvta_generic_to_shared(p);
}
__device__ __forceinline__ void ldm_x4(uint32_t& r0, uint32_t& r1, uint32_t& r2, uint32_t& r3,
                                       uint32_t addr) {
    asm volatile("ldmatrix.sync.aligned.m8n8.x4.shared.b16 {%0,%1,%2,%3}, [%4];\n"
                 : "=r"(r0), "=r"(r1), "=r"(r2), "=r"(r3) : "r"(addr));
}
__device__ __forceinline__ void ldm_x4_trans(uint32_t& r0, uint32_t& r1, uint32_t& r2, uint32_t& r3,
                                             uint32_t addr) {
    asm volatile("ldmatrix.sync.aligned.m8n8.x4.trans.shared.b16 {%0,%1,%2,%3}, [%4];\n"
                 : "=r"(r0), "=r"(r1), "=r"(r2), "=r"(r3) : "r"(addr));
}
__device__ __forceinline__ void mma_bf16(float* c, const uint32_t* a, const uint32_t* b) {
    asm volatile("mma.sync.aligned.m16n8k16.row.col.f32.bf16.bf16.f32 "
                 "{%0,%1,%2,%3}, {%4,%5,%6,%7}, {%8,%9}, {%0,%1,%2,%3};\n"
                 : "+f"(c[0]), "+f"(c[1]), "+f"(c[2]), "+f"(c[3])
                 : "r"(a[0]), "r"(a[1]), "r"(a[2]), "r"(a[3]), "r"(b[0]), "r"(b[1]));
}
__device__ __forceinline__ void mma_f16(float* c, const uint32_t* a, const uint32_t* b) {
    asm volatile("mma.sync.aligned.m16n8k16.row.col.f32.f16.f16.f32 "
                 "{%0,%1,%2,%3}, {%4,%5,%6,%7}, {%8,%9}, {%0,%1,%2,%3};\n"
                 : "+f"(c[0]), "+f"(c[1]), "+f"(c[2]), "+f"(c[3])
                 : "r"(a[0]), "r"(a[1]), "r"(a[2]), "r"(a[3]), "r"(b[0]), "r"(b[1]));
}
__device__ __forceinline__ void split2pack(float x0, float x1, uint32_t& h, uint32_t& l) {
    __nv_bfloat16 h0 = __float2bfloat16(x0), h1 = __float2bfloat16(x1);
    float r0 = x0 - __bfloat162float(h0);
    float r1 = x1 - __bfloat162float(h1);
    __nv_bfloat16 l0 = __float2bfloat16(r0), l1 = __float2bfloat16(r1);
    h = ((uint32_t)__bfloat16_as_ushort(h1) << 16) | (uint32_t)__bfloat16_as_ushort(h0);
    l = ((uint32_t)__bfloat16_as_ushort(l1) << 16) | (uint32_t)__bfloat16_as_ushort(l0);
}
__device__ __forceinline__ uint32_t packh2(float x0, float x1) {
    __half2 h = __floats2half2_rn(x0, x1);
    return *(uint32_t*)&h;
}
__device__ __forceinline__ uint32_t h2exp2(uint32_t x) {
    uint32_t r;
    asm("ex2.approx.f16x2 %0, %1;" : "=r"(r) : "r"(x));
    return r;
}
__device__ __forceinline__ uint32_t mask2(uint32_t w, int bp) {
    return (((w >> bp) & 1u) ? 0x0000FFFFu : 0u) |
           (((w >> (bp + 1)) & 1u) ? 0xFFFF0000u : 0u);
}
__device__ __forceinline__ void cp16(uint32_t dst, const void* src) {
    asm volatile("cp.async.cg.shared.global [%0], [%1], 16;\n" :: "r"(dst), "l"(src));
}
#define CP_COMMIT asm volatile("cp.async.commit_group;\n")
#define CP_WAIT0  asm volatile("cp.async.wait_group 0;\n" ::: "memory")
#define CP_WAIT1  asm volatile("cp.async.wait_group 1;\n" ::: "memory")

// ---------------- mask -> bitmask: persistent, throttled (overlaps QKV pipeline) ----------------
#define MB_CTAS  128
#define MB_WPI   8   // words per warp per iteration

__global__ void __launch_bounds__(256)
maskbits_kernel(const int* __restrict__ mask, uint32_t* __restrict__ bits)
{
    const int gw = blockIdx.x * 8 + (threadIdx.x >> 5);   // global warp id
    const int nw = MB_CTAS * 8;                            // 1024 warps
    const int lane = threadIdx.x & 31;
    // MWORDS / (nw*MB_WPI) = 4194304 / 8192 = 512 exact iterations
    for (size_t w0 = (size_t)gw * MB_WPI; w0 < MWORDS; w0 += (size_t)nw * MB_WPI) {
        int m[MB_WPI];
        #pragma unroll
        for (int j = 0; j < MB_WPI; j++)
            m[j] = mask[(w0 + j) * 32 + lane];
        #pragma unroll
        for (int j = 0; j < MB_WPI; j++) {
            uint32_t b = __ballot_sync(0xffffffff, m[j] != 0);
            if (lane == 0) bits[w0 + j] = b;
        }
    }
}

// ---------------- fused preconversion ----------------
__global__ void __launch_bounds__(256)
splitw4_kernel(const float* __restrict__ w0, const float* __restrict__ w1,
               const float* __restrict__ w2, const float* __restrict__ w3,
               __nv_bfloat16* __restrict__ hi, __nv_bfloat16* __restrict__ lo)
{
    const int y = blockIdx.y;
    const float* in = (y == 0) ? w0 : (y == 1) ? w1 : (y == 2) ? w2 : w3;
    size_t i = (size_t)blockIdx.x * 256 + threadIdx.x;
    float4 v = ((const float4*)in)[i];
    uint2 h, l;
    split2pack(v.x, v.y, h.x, l.x);
    split2pack(v.z, v.w, h.y, l.y);
    ((uint2*)(hi + y * W_N))[i] = h;
    ((uint2*)(lo + y * W_N))[i] = l;
}
__global__ void __launch_bounds__(256)
splita3_kernel(const float* __restrict__ a0, const float* __restrict__ a1,
               const float* __restrict__ a2,
               __nv_bfloat16* __restrict__ hi, __nv_bfloat16* __restrict__ lo)
{
    const int y = blockIdx.y;
    const float* in = (y == 0) ? a0 : (y == 1) ? a1 : a2;
    size_t i = (size_t)blockIdx.x * 256 + threadIdx.x;
    float4 v = ((const float4*)in)[i];
    uint2 h, l;
    split2pack(v.x, v.y, h.x, l.x);
    split2pack(v.z, v.w, h.y, l.y);
    ((uint2*)(hi + (size_t)y * ACT_N))[i] = h;
    ((uint2*)(lo + (size_t)y * ACT_N))[i] = l;
}

// ================= Fused QKV GEMM (R11-proven) =================
#define GSTR 40   // 32 + 8 pad (bf16 elems)

struct QSmem {
    __nv_bfloat16 Ah[2][128][GSTR], Al[2][128][GSTR];
    __nv_bfloat16 Wh[2][128][GSTR], Wl[2][128][GSTR];
};  // 81920 B

__global__ void __launch_bounds__(256, 2)
qkv_gemm_kernel(const __nv_bfloat16* __restrict__ xh_g, const __nv_bfloat16* __restrict__ xl_g,
                const __nv_bfloat16* __restrict__ wh_g, const __nv_bfloat16* __restrict__ wl_g,
                const float* __restrict__ b1q, const float* __restrict__ b2q,
                const float* __restrict__ b1k, const float* __restrict__ b2k,
                const float* __restrict__ b1v, const float* __restrict__ b2v,
                __half* __restrict__ out_g)
{
    extern __shared__ char smem_raw[];
    QSmem* S = (QSmem*)smem_raw;

    const int wsel = blockIdx.x >> 3;
    const int m0 = blockIdx.y * 128, n0 = (blockIdx.x & 7) * 128;
    const int tid = threadIdx.x;
    const int w = tid >> 5, lane = tid & 31;
    const int wm = w & 1, wn = w >> 1;
    const int rm = wm * 64, rn = wn * 32;
    const int lr = lane & 15, lc = (lane >> 4) << 3;
    const int tig = lane & 3, gid = lane >> 2;

    const __nv_bfloat16* srcAh = xh_g + (size_t)wsel * ACT_N + (size_t)m0 * D_MODEL;
    const __nv_bfloat16* srcAl = xl_g + (size_t)wsel * ACT_N + (size_t)m0 * D_MODEL;
    const __nv_bfloat16* srcWh = wh_g + (size_t)wsel * W_N + (size_t)n0 * D_MODEL;
    const __nv_bfloat16* srcWl = wl_g + (size_t)wsel * W_N + (size_t)n0 * D_MODEL;
    const float* b1 = (wsel == 0) ? b1q : (wsel == 1) ? b1k : b1v;
    const float* b2 = (wsel == 0) ? b2q : (wsel == 1) ? b2k : b2v;
    const float scale = (wsel == 0) ? QSCALE : 1.f;
    __half* oH = out_g + (size_t)wsel * ACT_N;

    float cf[4][4][4];
    #pragma unroll
    for (int mi = 0; mi < 4; mi++)
        #pragma unroll
        for (int ni = 0; ni < 4; ni++)
            #pragma unroll
            for (int e = 0; e < 4; e++) cf[mi][ni][e] = 0.f;

    auto stage = [&](int kt, int buf) {
        const int kofs = kt * 32;
        #pragma unroll
        for (int i = 0; i < 8; i++) {
            int idx = tid + i * 256;
            int arr = idx >> 9;
            int rem = idx & 511;
            int r = rem >> 2, c = (rem & 3) << 3;
            const __nv_bfloat16* src =
                (arr == 0 ? srcAh : arr == 1 ? srcAl : arr == 2 ? srcWh : srcWl)
                + (size_t)r * D_MODEL + kofs + c;
            uint32_t dst = smem_u32(
                arr == 0 ? (void*)&S->Ah[buf][r][c] : arr == 1 ? (void*)&S->Al[buf][r][c] :
                arr == 2 ? (void*)&S->Wh[buf][r][c] : (void*)&S->Wl[buf][r][c]);
            cp16(dst, src);
        }
        CP_COMMIT;
    };

    stage(0, 0);
    stage(1, 1);

    const int NKT = D_MODEL / 32;
    for (int kt = 0; kt < NKT; kt++) {
        const int buf = kt & 1;
        if (kt + 1 < NKT) { CP_WAIT1; } else { CP_WAIT0; }
        __syncthreads();

        #pragma unroll
        for (int ks = 0; ks < 2; ks++) {
            const int kb = ks * 16;
            uint32_t ah[4][4], al[4][4];
            #pragma unroll
            for (int mi = 0; mi < 4; mi++) {
                ldm_x4(ah[mi][0], ah[mi][1], ah[mi][2], ah[mi][3],
                       smem_u32(&S->Ah[buf][rm + mi * 16 + lr][kb + lc]));
                ldm_x4(al[mi][0], al[mi][1], al[mi][2], al[mi][3],
                       smem_u32(&S->Al[buf][rm + mi * 16 + lr][kb + lc]));
            }
            uint32_t bh[4][2], bl[4][2];
            #pragma unroll
            for (int g = 0; g < 2; g++) {
                uint32_t r0, r1, r2, r3;
                ldm_x4(r0, r1, r2, r3, smem_u32(&S->Wh[buf][rn + g * 16 + lr][kb + lc]));
                bh[2*g][0] = r0; bh[2*g+1][0] = r1; bh[2*g][1] = r2; bh[2*g+1][1] = r3;
                ldm_x4(r0, r1, r2, r3, smem_u32(&S->Wl[buf][rn + g * 16 + lr][kb + lc]));
                bl[2*g][0] = r0; bl[2*g+1][0] = r1; bl[2*g][1] = r2; bl[2*g+1][1] = r3;
            }
            #pragma unroll
            for (int mi = 0; mi < 4; mi++)
                #pragma unroll
                for (int ni = 0; ni < 4; ni++) {
                    mma_bf16(cf[mi][ni], ah[mi], bh[ni]);
                    mma_bf16(cf[mi][ni], ah[mi], bl[ni]);
                    mma_bf16(cf[mi][ni], al[mi], bh[ni]);
                }
        }
        __syncthreads();
        if (kt + 2 < NKT) stage(kt + 2, buf);
    }

    #pragma unroll
    for (int ni = 0; ni < 4; ni++) {
        const int c0 = rn + ni * 8 + tig * 2 + n0;
        const float bias0 = b1[c0] + b2[c0];
        const float bias1 = b1[c0 + 1] + b2[c0 + 1];
        #pragma unroll
        for (int mi = 0; mi < 4; mi++) {
            #pragma unroll
            for (int half = 0; half < 2; half++) {
                int m = m0 + rm + mi * 16 + gid + half * 8;
                float v0 = (cf[mi][ni][half * 2]     + bias0) * scale;
                float v1 = (cf[mi][ni][half * 2 + 1] + bias1) * scale;
                int bb = m >> 11, s = m & (SEQ - 1);
                int hh = c0 >> 6, d = c0 & (HS - 1);
                size_t off = (((size_t)(bb * NH + hh)) * SEQ + s) * HS + d;
                *(uint32_t*)&oH[off] = packh2(v0, v1);
            }
        }
    }
}

// ================= Y GEMM: fully async (attn out split-bf16 @ Wy^T + bias) =================
__global__ void __launch_bounds__(256, 2)
y_gemm_kernel(const __nv_bfloat16* __restrict__ Ahg, const __nv_bfloat16* __restrict__ Alg,
              const __nv_bfloat16* __restrict__ Whg, const __nv_bfloat16* __restrict__ Wlg,
              const float* __restrict__ b1, const float* __restrict__ b2,
              float* __restrict__ outF)
{
    extern __shared__ char smem_raw[];
    QSmem* S = (QSmem*)smem_raw;

    const int m0 = blockIdx.y * 128, n0 = blockIdx.x * 128;
    const int tid = threadIdx.x;
    const int w = tid >> 5, lane = tid & 31;
    const int wm = w & 1, wn = w >> 1;
    const int rm = wm * 64, rn = wn * 32;
    const int lr = lane & 15, lc = (lane >> 4) << 3;
    const int tig = lane & 3, gid = lane >> 2;

    const __nv_bfloat16* srcAh = Ahg + (size_t)m0 * D_MODEL;
    const __nv_bfloat16* srcAl = Alg + (size_t)m0 * D_MODEL;
    const __nv_bfloat16* srcWh = Whg + (size_t)n0 * D_MODEL;
    const __nv_bfloat16* srcWl = Wlg + (size_t)n0 * D_MODEL;

    float cf[4][4][4];
    #pragma unroll
    for (int mi = 0; mi < 4; mi++)
        #pragma unroll
        for (int ni = 0; ni < 4; ni++)
            #pragma unroll
            for (int e = 0; e < 4; e++) cf[mi][ni][e] = 0.f;

    auto stage = [&](int kt, int buf) {
        const int kofs = kt * 32;
        #pragma unroll
        for (int i = 0; i < 8; i++) {
            int idx = tid + i * 256;
            int arr = idx >> 9;
            int rem = idx & 511;
            int r = rem >> 2, c = (rem & 3) << 3;
            const __nv_bfloat16* src =
                (arr == 0 ? srcAh : arr == 1 ? srcAl : arr == 2 ? srcWh : srcWl)
                + (size_t)r * D_MODEL + kofs + c;
            uint32_t dst = smem_u32(
                arr == 0 ? (void*)&S->Ah[buf][r][c] : arr == 1 ? (void*)&S->Al[buf][r][c] :
                arr == 2 ? (void*)&S->Wh[buf][r][c] : (void*)&S->Wl[buf][r][c]);
            cp16(dst, src);
        }
        CP_COMMIT;
    };

    stage(0, 0);
    stage(1, 1);

    const int NKT = D_MODEL / 32;
    for (int kt = 0; kt < NKT; kt++) {
        const int buf = kt & 1;
        if (kt + 1 < NKT) { CP_WAIT1; } else { CP_WAIT0; }
        __syncthreads();

        #pragma unroll
        for (int ks = 0; ks < 2; ks++) {
            const int kb = ks * 16;
            uint32_t ah[4][4], al[4][4];
            #pragma unroll
            for (int mi = 0; mi < 4; mi++) {
                ldm_x4(ah[mi][0], ah[mi][1], ah[mi][2], ah[mi][3],
                       smem_u32(&S->Ah[buf][rm + mi * 16 + lr][kb + lc]));
                ldm_x4(al[mi][0], al[mi][1], al[mi][2], al[mi][3],
                       smem_u32(&S->Al[buf][rm + mi * 16 + lr][kb + lc]));
            }
            uint32_t bh[4][2], bl[4][2];
            #pragma unroll
            for (int g = 0; g < 2; g++) {
                uint32_t r0, r1, r2, r3;
                ldm_x4(r0, r1, r2, r3, smem_u32(&S->Wh[buf][rn + g * 16 + lr][kb + lc]));
                bh[2*g][0] = r0; bh[2*g+1][0] = r1; bh[2*g][1] = r2; bh[2*g+1][1] = r3;
                ldm_x4(r0, r1, r2, r3, smem_u32(&S->Wl[buf][rn + g * 16 + lr][kb + lc]));
                bl[2*g][0] = r0; bl[2*g+1][0] = r1; bl[2*g][1] = r2; bl[2*g+1][1] = r3;
            }
            #pragma unroll
            for (int mi = 0; mi < 4; mi++)
                #pragma unroll
                for (int ni = 0; ni < 4; ni++) {
                    mma_bf16(cf[mi][ni], ah[mi], bh[ni]);
                    mma_bf16(cf[mi][ni], ah[mi], bl[ni]);
                    mma_bf16(cf[mi][ni], al[mi], bh[ni]);
                }
        }
        __syncthreads();
        if (kt + 2 < NKT) stage(kt + 2, buf);
    }

    #pragma unroll
    for (int ni = 0; ni < 4; ni++) {
        const int c0 = n0 + rn + ni * 8 + tig * 2;
        const float bias0 = b1[c0] + b2[c0];
        const float bias1 = b1[c0 + 1] + b2[c0 + 1];
        #pragma unroll
        for (int mi = 0; mi < 4; mi++) {
            #pragma unroll
            for (int half = 0; half < 2; half++) {
                int m = m0 + rm + mi * 16 + gid + half * 8;
                *(float2*)&outF[(size_t)m * D_MODEL + c0] =
                    make_float2(cf[mi][ni][half * 2] + bias0, cf[mi][ni][half * 2 + 1] + bias1);
            }
        }
    }
}

// ================= Attention (R12-proven): 256 thr, 2 CTAs/SM =================
#define AT_SMEM (3*2*64*72*2)   // 55296 B

__global__ void __launch_bounds__(256, 2)
attn_kernel(const __half* __restrict__ qkv_g, const uint32_t* __restrict__ mbits,
            __nv_bfloat16* __restrict__ oh_g, __nv_bfloat16* __restrict__ ol_g)
{
    extern __shared__ char smem_raw[];
    typedef __half KVbuf[2][64][72];
    KVbuf* KV = (KVbuf*)smem_raw;

    const int tid = threadIdx.x;
    const int h = blockIdx.y, b = blockIdx.z;
    const int bh = b * NH + h;
    const int q0 = blockIdx.x * 128;
    const int w = tid >> 5, lane = tid & 31;
    const int lr = lane & 15, lc = (lane >> 4) << 3;
    const int tig = lane & 3, gid = lane >> 2;
    const int vr = ((lane >> 4) << 3) + (lane & 7), vc = lane & 8;

    const __half* qf_g = qkv_g;
    const __half* kf_g = qkv_g + ACT_N;
    const __half* vf_g = qkv_g + 2 * ACT_N;
    const size_t kvbase = (size_t)bh * SEQ * HS;

    {
        __half (*Qs)[72] = (__half (*)[72])&KV[0][0][0][0];
        #pragma unroll
        for (int j = 0; j < 4; j++) {
            int idx = tid + j * 256;
            int r = idx >> 3, c = (idx & 7) << 3;
            cp16(smem_u32(&Qs[r][c]), qf_g + kvbase + (size_t)(q0 + r) * HS + c);
        }
        CP_COMMIT; CP_WAIT0;
        __syncthreads();
    }
    uint32_t qf[4][4];
    {
        __half (*Qs)[72] = (__half (*)[72])&KV[0][0][0][0];
        #pragma unroll
        for (int ks = 0; ks < 4; ks++)
            ldm_x4(qf[ks][0], qf[ks][1], qf[ks][2], qf[ks][3],
                   smem_u32(&Qs[w * 16 + lr][ks * 16 + lc]));
        __syncthreads();
    }

    float oacc[8][4];
    #pragma unroll
    for (int nt = 0; nt < 8; nt++)
        #pragma unroll
        for (int e = 0; e < 4; e++) oacc[nt][e] = 0.f;
    float rsacc[4] = {0.f, 0.f, 0.f, 0.f};

    const uint32_t* mrow0 = mbits + ((size_t)(bh * SEQ) + q0 + w * 16 + gid) * 64;
    const uint32_t* mrow1 = mrow0 + 8 * 64;

    auto stage_kv = [&](int t, int buf) {
        #pragma unroll
        for (int j = 0; j < 4; j++) {
            int idx = tid + j * 256;
            int a = idx >> 9, rem = idx & 511;
            int r = rem >> 3, c = (rem & 7) << 3;
            const __half* src = (a ? vf_g : kf_g) + kvbase + (size_t)(t * 64 + r) * HS + c;
            cp16(smem_u32(&KV[buf][a][r][c]), src);
        }
        CP_COMMIT;
    };

    stage_kv(0, 0);
    stage_kv(1, 1);

    const uint32_t vones[2] = {0x3C003C00u, 0x3C003C00u};
    const int NT = SEQ / 64;

    uint32_t mw0a = mrow0[0], mw0b = mrow0[1];
    uint32_t mw1a = mrow1[0], mw1b = mrow1[1];

    for (int t = 0; t < NT; t++) {
        const int buf = t % 3;
        if (t + 1 < NT) { CP_WAIT1; } else { CP_WAIT0; }
        __syncthreads();
        if (t + 2 < NT) stage_kv(t + 2, (t + 2) % 3);

        uint32_t n0a = 0, n0b = 0, n1a = 0, n1b = 0;
        if (t + 1 < NT) {
            n0a = mrow0[(t + 1) * 2]; n0b = mrow0[(t + 1) * 2 + 1];
            n1a = mrow1[(t + 1) * 2]; n1b = mrow1[(t + 1) * 2 + 1];
        }

        const __half (*Kf)[72] = KV[buf][0];
        const __half (*Vf)[72] = KV[buf][1];

        float sc[8][4];
        #pragma unroll
        for (int nt = 0; nt < 8; nt++)
            #pragma unroll
            for (int e = 0; e < 4; e++) sc[nt][e] = 0.f;

        #pragma unroll
        for (int ks = 0; ks < 4; ks++) {
            const int kb = ks * 16;
            uint32_t kf[8][2];
            #pragma unroll
            for (int g = 0; g < 4; g++) {
                uint32_t r0, r1, r2, r3;
                ldm_x4(r0, r1, r2, r3, smem_u32(&Kf[g * 16 + lr][kb + lc]));
                kf[2*g][0] = r0; kf[2*g+1][0] = r1; kf[2*g][1] = r2; kf[2*g+1][1] = r3;
            }
            #pragma unroll
            for (int nt = 0; nt < 8; nt++)
                mma_f16(sc[nt], qf[ks], kf[nt]);
        }

        uint32_t pf[4][4];
        #pragma unroll
        for (int nt = 0; nt < 8; nt++) {
            const uint32_t w0 = (nt < 4) ? mw0a : mw0b;
            const uint32_t w1 = (nt < 4) ? mw1a : mw1b;
            const int bp = (nt & 3) * 8 + tig * 2;
            uint32_t e01 = h2exp2(packh2(sc[nt][0], sc[nt][1])) & mask2(w0, bp);
            uint32_t e23 = h2exp2(packh2(sc[nt][2], sc[nt][3])) & mask2(w1, bp);
            pf[nt >> 1][(nt & 1) * 2]     = e01;
            pf[nt >> 1][(nt & 1) * 2 + 1] = e23;
        }

        #pragma unroll
        for (int kp = 0; kp < 4; kp++) {
            mma_f16(rsacc, pf[kp], vones);
            const int krow = kp * 16 + vr;
            #pragma unroll
            for (int g = 0; g < 4; g++) {
                uint32_t vf[2][2];
                uint32_t r0, r1, r2, r3;
                ldm_x4_trans(r0, r1, r2, r3, smem_u32(&Vf[krow][g * 16 + vc]));
                vf[0][0] = r0; vf[1][0] = r1; vf[0][1] = r2; vf[1][1] = r3;
                mma_f16(oacc[2*g + 0], pf[kp], vf[0]);
                mma_f16(oacc[2*g + 1], pf[kp], vf[1]);
            }
        }
        mw0a = n0a; mw0b = n0b; mw1a = n1a; mw1b = n1b;
    }

    const float inv0 = 1.f / rsacc[0], inv1 = 1.f / rsacc[2];
    const size_t orow0 = (size_t)(b * SEQ + q0 + w * 16 + gid) * D_MODEL + h * HS;
    const size_t orow1 = orow0 + 8 * D_MODEL;
    #pragma unroll
    for (int nt = 0; nt < 8; nt++) {
        const int c = nt * 8 + tig * 2;
        uint32_t hh, ll;
        split2pack(oacc[nt][0] * inv0, oacc[nt][1] * inv0, hh, ll);
        *(uint32_t*)&oh_g[orow0 + c] = hh;
        *(uint32_t*)&ol_g[orow0 + c] = ll;
        split2pack(oacc[nt][2] * inv1, oacc[nt][3] * inv1, hh, ll);
        *(uint32_t*)&oh_g[orow1 + c] = hh;
        *(uint32_t*)&ol_g[orow1 + c] = ll;
    }
}

// ---------------- launch ----------------
extern "C" void kernel_launch(void* const* d_in, const int* in_sizes, int n_in,
                              void* d_out, int out_size)
{
    const float* queries = (const float*)d_in[0];
    const float* keys    = (const float*)d_in[1];
    const float* values  = (const float*)d_in[2];
    const int*   mask    = (const int*)d_in[3];
    const float* Wq = (const float*)d_in[4];  const float* bq = (const float*)d_in[5];
    const float* Wk = (const float*)d_in[6];  const float* bk = (const float*)d_in[7];
    const float* Wv = (const float*)d_in[8];  const float* bv = (const float*)d_in[9];
    const float* Wy = (const float*)d_in[10]; const float* by = (const float*)d_in[11];
    const float* bq2 = (const float*)d_in[12];
    const float* bk2 = (const float*)d_in[13];
    const float* bv2 = (const float*)d_in[14];
    const float* by2 = (const float*)d_in[15];
    float* out = (float*)d_out;

    __nv_bfloat16 *xh, *xl, *wh, *wl, *oh, *ol;
    __half* qkvf;
    uint32_t* mb;
    cudaGetSymbolAddress((void**)&xh, g_xh);   cudaGetSymbolAddress((void**)&xl, g_xl);
    cudaGetSymbolAddress((void**)&wh, g_wh);   cudaGetSymbolAddress((void**)&wl, g_wl);
    cudaGetSymbolAddress((void**)&oh, g_oh);   cudaGetSymbolAddress((void**)&ol, g_ol);
    cudaGetSymbolAddress((void**)&qkvf, g_qkvf);
    cudaGetSymbolAddress((void**)&mb, g_mbits);

    static int attr_set = 0;
    static cudaStream_t s2 = nullptr;
    static cudaEvent_t evFork = nullptr, evJoin = nullptr;
    if (!attr_set) {
        cudaFuncSetAttribute(qkv_gemm_kernel, cudaFuncAttributeMaxDynamicSharedMemorySize,
                             (int)sizeof(QSmem));
        cudaFuncSetAttribute(y_gemm_kernel, cudaFuncAttributeMaxDynamicSharedMemorySize,
                             (int)sizeof(QSmem));
        cudaFuncSetAttribute(attn_kernel, cudaFuncAttributeMaxDynamicSharedMemorySize,
                             AT_SMEM);
        if (cudaStreamCreateWithFlags(&s2, cudaStreamNonBlocking) != cudaSuccess) s2 = nullptr;
        if (s2) {
            if (cudaEventCreateWithFlags(&evFork, cudaEventDisableTiming) != cudaSuccess ||
                cudaEventCreateWithFlags(&evJoin, cudaEventDisableTiming) != cudaSuccess) {
                s2 = nullptr;
            }
        }
        attr_set = 1;
    }

    const int W4 = (int)(W_N / 4), A4 = (int)(ACT_N / 4);
    const bool fork = (s2 != nullptr);

    // ---- fork: persistent throttled mask bitpack (128 CTAs) coexists with QKV pipeline ----
    if (fork) {
        cudaEventRecord(evFork, 0);
        cudaStreamWaitEvent(s2, evFork, 0);
        maskbits_kernel<<<MB_CTAS, 256, 0, s2>>>(mask, mb);
        cudaEventRecord(evJoin, s2);
    } else {
        maskbits_kernel<<<MB_CTAS, 256>>>(mask, mb);
    }

    // ---- main stream: preconversion + fused QKV GEMM (tensor-bound) ----
    splitw4_kernel<<<dim3(W4 / 256, 4), 256>>>(Wq, Wk, Wv, Wy, wh, wl);
    splita3_kernel<<<dim3(A4 / 256, 3), 256>>>(queries, keys, values, xh, xl);

    dim3 qgrid(24, MROWS / 128);
    qkv_gemm_kernel<<<qgrid, 256, sizeof(QSmem)>>>(xh, xl, wh, wl,
                                                   bq, bq2, bk, bk2, bv, bv2, qkvf);

    // ---- join before attention (needs mask bits) ----
    if (fork) cudaStreamWaitEvent(0, evJoin, 0);

    dim3 agrid(SEQ / 128, NH, BATCH);
    attn_kernel<<<agrid, 256, AT_SMEM>>>(qkvf, mb, oh, ol);

    dim3 ygrid(D_MODEL / 128, MROWS / 128);
    y_gemm_kernel<<<ygrid, 256, sizeof(QSmem)>>>(oh, ol, wh + 3 * W_N, wl + 3 * W_N,
                                                 by, by2, out);
}

// round 15
// speedup vs baseline: 1.1174x; 1.0001x over previous
#include <cuda_runtime.h>
#include <cuda_bf16.h>
#include <cuda_fp16.h>
#include <cstdint>

#define D_MODEL 1024
#define NH      16
#define HS      64
#define BATCH   2
#define SEQ     2048
#define MROWS   (BATCH*SEQ)   // 4096
#define ACT_N   ((size_t)MROWS*D_MODEL)   // 4M
#define W_N     ((size_t)D_MODEL*D_MODEL) // 1M
#define MWORDS  ((size_t)BATCH*NH*SEQ*SEQ/32)  // 4,194,304
#define QSCALE  0.18033688011112042f   // 0.125 * log2(e)

// ---------------- scratch (no allocations allowed) ----------------
__device__ __nv_bfloat16 g_xh[3][ACT_N], g_xl[3][ACT_N];  // preconverted activations
__device__ __nv_bfloat16 g_wh[4][W_N],  g_wl[4][W_N];     // preconverted weights
__device__ __half g_qkvf[3][ACT_N];   // q/k/v head-split [B,H,S,HS] fp16 (q pre-scaled)
__device__ __nv_bfloat16 g_oh[ACT_N], g_ol[ACT_N];        // attn out split-bf16, merged
__device__ uint32_t g_mbits[MWORDS];

// ---------------- helpers ----------------
__device__ __forceinline__ uint32_t smem_u32(const void* p) {
    return (uint32_t)__cvta_generic_to_shared(p);
}
__device__ __forceinline__ void ldm_x4(uint32_t& r0, uint32_t& r1, uint32_t& r2, uint32_t& r3,
                                       uint32_t addr) {
    asm volatile("ldmatrix.sync.aligned.m8n8.x4.shared.b16 {%0,%1,%2,%3}, [%4];\n"
                 : "=r"(r0), "=r"(r1), "=r"(r2), "=r"(r3) : "r"(addr));
}
__device__ __forceinline__ void ldm_x4_trans(uint32_t& r0, uint32_t& r1, uint32_t& r2, uint32_t& r3,
                                             uint32_t addr) {
    asm volatile("ldmatrix.sync.aligned.m8n8.x4.trans.shared.b16 {%0,%1,%2,%3}, [%4];\n"
                 : "=r"(r0), "=r"(r1), "=r"(r2), "=r"(r3) : "r"(addr));
}
__device__ __forceinline__ void mma_bf16(float* c, const uint32_t* a, const uint32_t* b) {
    asm volatile("mma.sync.aligned.m16n8k16.row.col.f32.bf16.bf16.f32 "
                 "{%0,%1,%2,%3}, {%4,%5,%6,%7}, {%8,%9}, {%0,%1,%2,%3};\n"
                 : "+f"(c[0]), "+f"(c[1]), "+f"(c[2]), "+f"(c[3])
                 : "r"(a[0]), "r"(a[1]), "r"(a[2]), "r"(a[3]), "r"(b[0]), "r"(b[1]));
}
__device__ __forceinline__ void mma_f16(float* c, const uint32_t* a, const uint32_t* b) {
    asm volatile("mma.sync.aligned.m16n8k16.row.col.f32.f16.f16.f32 "
                 "{%0,%1,%2,%3}, {%4,%5,%6,%7}, {%8,%9}, {%0,%1,%2,%3};\n"
                 : "+f"(c[0]), "+f"(c[1]), "+f"(c[2]), "+f"(c[3])
                 : "r"(a[0]), "r"(a[1]), "r"(a[2]), "r"(a[3]), "r"(b[0]), "r"(b[1]));
}
__device__ __forceinline__ void split2pack(float x0, float x1, uint32_t& h, uint32_t& l) {
    __nv_bfloat16 h0 = __float2bfloat16(x0), h1 = __float2bfloat16(x1);
    float r0 = x0 - __bfloat162float(h0);
    float r1 = x1 - __bfloat162float(h1);
    __nv_bfloat16 l0 = __float2bfloat16(r0), l1 = __float2bfloat16(r1);
    h = ((uint32_t)__bfloat16_as_ushort(h1) << 16) | (uint32_t)__bfloat16_as_ushort(h0);
    l = ((uint32_t)__bfloat16_as_ushort(l1) << 16) | (uint32_t)__bfloat16_as_ushort(l0);
}
__device__ __forceinline__ uint32_t packh2(float x0, float x1) {
    __half2 h = __floats2half2_rn(x0, x1);
    return *(uint32_t*)&h;
}
__device__ __forceinline__ uint32_t h2exp2(uint32_t x) {
    uint32_t r;
    asm("ex2.approx.f16x2 %0, %1;" : "=r"(r) : "r"(x));
    return r;
}
__device__ __forceinline__ uint32_t mask2(uint32_t w, int bp) {
    return (((w >> bp) & 1u) ? 0x0000FFFFu : 0u) |
           (((w >> (bp + 1)) & 1u) ? 0xFFFF0000u : 0u);
}
__device__ __forceinline__ void cp16(uint32_t dst, const void* src) {
    asm volatile("cp.async.cg.shared.global [%0], [%1], 16;\n" :: "r"(dst), "l"(src));
}
#define CP_COMMIT asm volatile("cp.async.commit_group;\n")
#define CP_WAIT0  asm volatile("cp.async.wait_group 0;\n" ::: "memory")
#define CP_WAIT1  asm volatile("cp.async.wait_group 1;\n" ::: "memory")

// ---------------- mask -> bitmask: persistent, throttled (overlaps QKV pipeline) ----------------
#define MB_CTAS  128
#define MB_WPI   8

__global__ void __launch_bounds__(256)
maskbits_kernel(const int* __restrict__ mask, uint32_t* __restrict__ bits)
{
    const int gw = blockIdx.x * 8 + (threadIdx.x >> 5);
    const int nw = MB_CTAS * 8;
    const int lane = threadIdx.x & 31;
    for (size_t w0 = (size_t)gw * MB_WPI; w0 < MWORDS; w0 += (size_t)nw * MB_WPI) {
        int m[MB_WPI];
        #pragma unroll
        for (int j = 0; j < MB_WPI; j++)
            m[j] = mask[(w0 + j) * 32 + lane];
        #pragma unroll
        for (int j = 0; j < MB_WPI; j++) {
            uint32_t b = __ballot_sync(0xffffffff, m[j] != 0);
            if (lane == 0) bits[w0 + j] = b;
        }
    }
}

// ---------------- fused preconversion ----------------
__global__ void __launch_bounds__(256)
splitw4_kernel(const float* __restrict__ w0, const float* __restrict__ w1,
               const float* __restrict__ w2, const float* __restrict__ w3,
               __nv_bfloat16* __restrict__ hi, __nv_bfloat16* __restrict__ lo)
{
    const int y = blockIdx.y;
    const float* in = (y == 0) ? w0 : (y == 1) ? w1 : (y == 2) ? w2 : w3;
    size_t i = (size_t)blockIdx.x * 256 + threadIdx.x;
    float4 v = ((const float4*)in)[i];
    uint2 h, l;
    split2pack(v.x, v.y, h.x, l.x);
    split2pack(v.z, v.w, h.y, l.y);
    ((uint2*)(hi + y * W_N))[i] = h;
    ((uint2*)(lo + y * W_N))[i] = l;
}
__global__ void __launch_bounds__(256)
splita3_kernel(const float* __restrict__ a0, const float* __restrict__ a1,
               const float* __restrict__ a2,
               __nv_bfloat16* __restrict__ hi, __nv_bfloat16* __restrict__ lo)
{
    const int y = blockIdx.y;
    const float* in = (y == 0) ? a0 : (y == 1) ? a1 : a2;
    size_t i = (size_t)blockIdx.x * 256 + threadIdx.x;
    float4 v = ((const float4*)in)[i];
    uint2 h, l;
    split2pack(v.x, v.y, h.x, l.x);
    split2pack(v.z, v.w, h.y, l.y);
    ((uint2*)(hi + (size_t)y * ACT_N))[i] = h;
    ((uint2*)(lo + (size_t)y * ACT_N))[i] = l;
}

// ================= Fused QKV GEMM (R11-proven) =================
#define GSTR 40   // 32 + 8 pad (bf16 elems)

struct QSmem {
    __nv_bfloat16 Ah[2][128][GSTR], Al[2][128][GSTR];
    __nv_bfloat16 Wh[2][128][GSTR], Wl[2][128][GSTR];
};  // 81920 B

__global__ void __launch_bounds__(256, 2)
qkv_gemm_kernel(const __nv_bfloat16* __restrict__ xh_g, const __nv_bfloat16* __restrict__ xl_g,
                const __nv_bfloat16* __restrict__ wh_g, const __nv_bfloat16* __restrict__ wl_g,
                const float* __restrict__ b1q, const float* __restrict__ b2q,
                const float* __restrict__ b1k, const float* __restrict__ b2k,
                const float* __restrict__ b1v, const float* __restrict__ b2v,
                __half* __restrict__ out_g)
{
    extern __shared__ char smem_raw[];
    QSmem* S = (QSmem*)smem_raw;

    const int wsel = blockIdx.x >> 3;
    const int m0 = blockIdx.y * 128, n0 = (blockIdx.x & 7) * 128;
    const int tid = threadIdx.x;
    const int w = tid >> 5, lane = tid & 31;
    const int wm = w & 1, wn = w >> 1;
    const int rm = wm * 64, rn = wn * 32;
    const int lr = lane & 15, lc = (lane >> 4) << 3;
    const int tig = lane & 3, gid = lane >> 2;

    const __nv_bfloat16* srcAh = xh_g + (size_t)wsel * ACT_N + (size_t)m0 * D_MODEL;
    const __nv_bfloat16* srcAl = xl_g + (size_t)wsel * ACT_N + (size_t)m0 * D_MODEL;
    const __nv_bfloat16* srcWh = wh_g + (size_t)wsel * W_N + (size_t)n0 * D_MODEL;
    const __nv_bfloat16* srcWl = wl_g + (size_t)wsel * W_N + (size_t)n0 * D_MODEL;
    const float* b1 = (wsel == 0) ? b1q : (wsel == 1) ? b1k : b1v;
    const float* b2 = (wsel == 0) ? b2q : (wsel == 1) ? b2k : b2v;
    const float scale = (wsel == 0) ? QSCALE : 1.f;
    __half* oH = out_g + (size_t)wsel * ACT_N;

    float cf[4][4][4];
    #pragma unroll
    for (int mi = 0; mi < 4; mi++)
        #pragma unroll
        for (int ni = 0; ni < 4; ni++)
            #pragma unroll
            for (int e = 0; e < 4; e++) cf[mi][ni][e] = 0.f;

    auto stage = [&](int kt, int buf) {
        const int kofs = kt * 32;
        #pragma unroll
        for (int i = 0; i < 8; i++) {
            int idx = tid + i * 256;
            int arr = idx >> 9;
            int rem = idx & 511;
            int r = rem >> 2, c = (rem & 3) << 3;
            const __nv_bfloat16* src =
                (arr == 0 ? srcAh : arr == 1 ? srcAl : arr == 2 ? srcWh : srcWl)
                + (size_t)r * D_MODEL + kofs + c;
            uint32_t dst = smem_u32(
                arr == 0 ? (void*)&S->Ah[buf][r][c] : arr == 1 ? (void*)&S->Al[buf][r][c] :
                arr == 2 ? (void*)&S->Wh[buf][r][c] : (void*)&S->Wl[buf][r][c]);
            cp16(dst, src);
        }
        CP_COMMIT;
    };

    stage(0, 0);
    stage(1, 1);

    const int NKT = D_MODEL / 32;
    for (int kt = 0; kt < NKT; kt++) {
        const int buf = kt & 1;
        if (kt + 1 < NKT) { CP_WAIT1; } else { CP_WAIT0; }
        __syncthreads();

        #pragma unroll
        for (int ks = 0; ks < 2; ks++) {
            const int kb = ks * 16;
            uint32_t ah[4][4], al[4][4];
            #pragma unroll
            for (int mi = 0; mi < 4; mi++) {
                ldm_x4(ah[mi][0], ah[mi][1], ah[mi][2], ah[mi][3],
                       smem_u32(&S->Ah[buf][rm + mi * 16 + lr][kb + lc]));
                ldm_x4(al[mi][0], al[mi][1], al[mi][2], al[mi][3],
                       smem_u32(&S->Al[buf][rm + mi * 16 + lr][kb + lc]));
            }
            uint32_t bh[4][2], bl[4][2];
            #pragma unroll
            for (int g = 0; g < 2; g++) {
                uint32_t r0, r1, r2, r3;
                ldm_x4(r0, r1, r2, r3, smem_u32(&S->Wh[buf][rn + g * 16 + lr][kb + lc]));
                bh[2*g][0] = r0; bh[2*g+1][0] = r1; bh[2*g][1] = r2; bh[2*g+1][1] = r3;
                ldm_x4(r0, r1, r2, r3, smem_u32(&S->Wl[buf][rn + g * 16 + lr][kb + lc]));
                bl[2*g][0] = r0; bl[2*g+1][0] = r1; bl[2*g][1] = r2; bl[2*g+1][1] = r3;
            }
            #pragma unroll
            for (int mi = 0; mi < 4; mi++)
                #pragma unroll
                for (int ni = 0; ni < 4; ni++) {
                    mma_bf16(cf[mi][ni], ah[mi], bh[ni]);
                    mma_bf16(cf[mi][ni], ah[mi], bl[ni]);
                    mma_bf16(cf[mi][ni], al[mi], bh[ni]);
                }
        }
        __syncthreads();
        if (kt + 2 < NKT) stage(kt + 2, buf);
    }

    #pragma unroll
    for (int ni = 0; ni < 4; ni++) {
        const int c0 = rn + ni * 8 + tig * 2 + n0;
        const float bias0 = b1[c0] + b2[c0];
        const float bias1 = b1[c0 + 1] + b2[c0 + 1];
        #pragma unroll
        for (int mi = 0; mi < 4; mi++) {
            #pragma unroll
            for (int half = 0; half < 2; half++) {
                int m = m0 + rm + mi * 16 + gid + half * 8;
                float v0 = (cf[mi][ni][half * 2]     + bias0) * scale;
                float v1 = (cf[mi][ni][half * 2 + 1] + bias1) * scale;
                int bb = m >> 11, s = m & (SEQ - 1);
                int hh = c0 >> 6, d = c0 & (HS - 1);
                size_t off = (((size_t)(bb * NH + hh)) * SEQ + s) * HS + d;
                *(uint32_t*)&oH[off] = packh2(v0, v1);
            }
        }
    }
}

// ================= Y GEMM: fully async (attn out split-bf16 @ Wy^T + bias) =================
__global__ void __launch_bounds__(256, 2)
y_gemm_kernel(const __nv_bfloat16* __restrict__ Ahg, const __nv_bfloat16* __restrict__ Alg,
              const __nv_bfloat16* __restrict__ Whg, const __nv_bfloat16* __restrict__ Wlg,
              const float* __restrict__ b1, const float* __restrict__ b2,
              float* __restrict__ outF)
{
    extern __shared__ char smem_raw[];
    QSmem* S = (QSmem*)smem_raw;

    const int m0 = blockIdx.y * 128, n0 = blockIdx.x * 128;
    const int tid = threadIdx.x;
    const int w = tid >> 5, lane = tid & 31;
    const int wm = w & 1, wn = w >> 1;
    const int rm = wm * 64, rn = wn * 32;
    const int lr = lane & 15, lc = (lane >> 4) << 3;
    const int tig = lane & 3, gid = lane >> 2;

    const __nv_bfloat16* srcAh = Ahg + (size_t)m0 * D_MODEL;
    const __nv_bfloat16* srcAl = Alg + (size_t)m0 * D_MODEL;
    const __nv_bfloat16* srcWh = Whg + (size_t)n0 * D_MODEL;
    const __nv_bfloat16* srcWl = Wlg + (size_t)n0 * D_MODEL;

    float cf[4][4][4];
    #pragma unroll
    for (int mi = 0; mi < 4; mi++)
        #pragma unroll
        for (int ni = 0; ni < 4; ni++)
            #pragma unroll
            for (int e = 0; e < 4; e++) cf[mi][ni][e] = 0.f;

    auto stage = [&](int kt, int buf) {
        const int kofs = kt * 32;
        #pragma unroll
        for (int i = 0; i < 8; i++) {
            int idx = tid + i * 256;
            int arr = idx >> 9;
            int rem = idx & 511;
            int r = rem >> 2, c = (rem & 3) << 3;
            const __nv_bfloat16* src =
                (arr == 0 ? srcAh : arr == 1 ? srcAl : arr == 2 ? srcWh : srcWl)
                + (size_t)r * D_MODEL + kofs + c;
            uint32_t dst = smem_u32(
                arr == 0 ? (void*)&S->Ah[buf][r][c] : arr == 1 ? (void*)&S->Al[buf][r][c] :
                arr == 2 ? (void*)&S->Wh[buf][r][c] : (void*)&S->Wl[buf][r][c]);
            cp16(dst, src);
        }
        CP_COMMIT;
    };

    stage(0, 0);
    stage(1, 1);

    const int NKT = D_MODEL / 32;
    for (int kt = 0; kt < NKT; kt++) {
        const int buf = kt & 1;
        if (kt + 1 < NKT) { CP_WAIT1; } else { CP_WAIT0; }
        __syncthreads();

        #pragma unroll
        for (int ks = 0; ks < 2; ks++) {
            const int kb = ks * 16;
            uint32_t ah[4][4], al[4][4];
            #pragma unroll
            for (int mi = 0; mi < 4; mi++) {
                ldm_x4(ah[mi][0], ah[mi][1], ah[mi][2], ah[mi][3],
                       smem_u32(&S->Ah[buf][rm + mi * 16 + lr][kb + lc]));
                ldm_x4(al[mi][0], al[mi][1], al[mi][2], al[mi][3],
                       smem_u32(&S->Al[buf][rm + mi * 16 + lr][kb + lc]));
            }
            uint32_t bh[4][2], bl[4][2];
            #pragma unroll
            for (int g = 0; g < 2; g++) {
                uint32_t r0, r1, r2, r3;
                ldm_x4(r0, r1, r2, r3, smem_u32(&S->Wh[buf][rn + g * 16 + lr][kb + lc]));
                bh[2*g][0] = r0; bh[2*g+1][0] = r1; bh[2*g][1] = r2; bh[2*g+1][1] = r3;
                ldm_x4(r0, r1, r2, r3, smem_u32(&S->Wl[buf][rn + g * 16 + lr][kb + lc]));
                bl[2*g][0] = r0; bl[2*g+1][0] = r1; bl[2*g][1] = r2; bl[2*g+1][1] = r3;
            }
            #pragma unroll
            for (int mi = 0; mi < 4; mi++)
                #pragma unroll
                for (int ni = 0; ni < 4; ni++) {
                    mma_bf16(cf[mi][ni], ah[mi], bh[ni]);
                    mma_bf16(cf[mi][ni], ah[mi], bl[ni]);
                    mma_bf16(cf[mi][ni], al[mi], bh[ni]);
                }
        }
        __syncthreads();
        if (kt + 2 < NKT) stage(kt + 2, buf);
    }

    #pragma unroll
    for (int ni = 0; ni < 4; ni++) {
        const int c0 = n0 + rn + ni * 8 + tig * 2;
        const float bias0 = b1[c0] + b2[c0];
        const float bias1 = b1[c0 + 1] + b2[c0 + 1];
        #pragma unroll
        for (int mi = 0; mi < 4; mi++) {
            #pragma unroll
            for (int half = 0; half < 2; half++) {
                int m = m0 + rm + mi * 16 + gid + half * 8;
                *(float2*)&outF[(size_t)m * D_MODEL + c0] =
                    make_float2(cf[mi][ni][half * 2] + bias0, cf[mi][ni][half * 2 + 1] + bias1);
            }
        }
    }
}

// ================= Attention: 128-key tiles, 2-buf ring, cross-half pipeline =================
// 8 warps x 16 q-rows. Tile order: QK0 -> pack0 -> QK1 -> PV0 -> pack1 -> PV1 so the
// tensor pipe has independent work while each softmax chain completes. 1 barrier/tile (16).
#define AT_SMEM (2*2*128*72*2)   // 73728 B -> 2 CTAs/SM

__global__ void __launch_bounds__(256, 2)
attn_kernel(const __half* __restrict__ qkv_g, const uint32_t* __restrict__ mbits,
            __nv_bfloat16* __restrict__ oh_g, __nv_bfloat16* __restrict__ ol_g)
{
    extern __shared__ char smem_raw[];
    typedef __half KVbuf[2][128][72];
    KVbuf* KV = (KVbuf*)smem_raw;    // KV[buf][arr][row][col], buf 0..1

    const int tid = threadIdx.x;
    const int h = blockIdx.y, b = blockIdx.z;
    const int bh = b * NH + h;
    const int q0 = blockIdx.x * 128;
    const int w = tid >> 5, lane = tid & 31;
    const int lr = lane & 15, lc = (lane >> 4) << 3;
    const int tig = lane & 3, gid = lane >> 2;
    const int vr = ((lane >> 4) << 3) + (lane & 7), vc = lane & 8;

    const __half* qf_g = qkv_g;
    const __half* kf_g = qkv_g + ACT_N;
    const __half* vf_g = qkv_g + 2 * ACT_N;
    const size_t kvbase = (size_t)bh * SEQ * HS;

    // ---- stage Q (128x64) into KV[0] flat region, grab frags, release ----
    {
        __half (*Qs)[72] = (__half (*)[72])&KV[0][0][0][0];
        #pragma unroll
        for (int j = 0; j < 4; j++) {
            int idx = tid + j * 256;
            int r = idx >> 3, c = (idx & 7) << 3;
            cp16(smem_u32(&Qs[r][c]), qf_g + kvbase + (size_t)(q0 + r) * HS + c);
        }
        CP_COMMIT; CP_WAIT0;
        __syncthreads();
    }
    uint32_t qf[4][4];
    {
        __half (*Qs)[72] = (__half (*)[72])&KV[0][0][0][0];
        #pragma unroll
        for (int ks = 0; ks < 4; ks++)
            ldm_x4(qf[ks][0], qf[ks][1], qf[ks][2], qf[ks][3],
                   smem_u32(&Qs[w * 16 + lr][ks * 16 + lc]));
        __syncthreads();
    }

    float oacc[8][4];
    #pragma unroll
    for (int nt = 0; nt < 8; nt++)
        #pragma unroll
        for (int e = 0; e < 4; e++) oacc[nt][e] = 0.f;
    float rsacc[4] = {0.f, 0.f, 0.f, 0.f};

    // 64 mask words per row; tile t covers words t*4 .. t*4+3
    const uint32_t* mrow0 = mbits + ((size_t)(bh * SEQ) + q0 + w * 16 + gid) * 64;
    const uint32_t* mrow1 = mrow0 + 8 * 64;

    auto stage_kv = [&](int t, int buf) {
        #pragma unroll
        for (int j = 0; j < 8; j++) {
            int idx = tid + j * 256;               // 0..2047
            int a = idx >> 10, rem = idx & 1023;
            int r = rem >> 3, c = (rem & 7) << 3;
            const __half* src = (a ? vf_g : kf_g) + kvbase + (size_t)(t * 128 + r) * HS + c;
            cp16(smem_u32(&KV[buf][a][r][c]), src);
        }
        CP_COMMIT;
    };

    stage_kv(0, 0);

    const uint32_t vones[2] = {0x3C003C00u, 0x3C003C00u};
    const int NT = SEQ / 128;   // 16

    for (int t = 0; t < NT; t++) {
        CP_WAIT0;
        __syncthreads();                      // tile t ready; prev tile fully consumed
        if (t + 1 < NT) stage_kv(t + 1, (t + 1) & 1);

        const __half (*Kf)[72] = KV[t & 1][0];
        const __half (*Vf)[72] = KV[t & 1][1];

        // mask words for this tile (L2-resident; hidden under QK0)
        uint32_t m0[4], m1[4];
        #pragma unroll
        for (int j = 0; j < 4; j++) { m0[j] = mrow0[t * 4 + j]; m1[j] = mrow1[t * 4 + j]; }

        // ---- QK half0 (keys 0..63) ----
        float sc[8][4];
        #pragma unroll
        for (int nt = 0; nt < 8; nt++)
            #pragma unroll
            for (int e = 0; e < 4; e++) sc[nt][e] = 0.f;
        #pragma unroll
        for (int ks = 0; ks < 4; ks++) {
            const int kb = ks * 16;
            uint32_t kf[8][2];
            #pragma unroll
            for (int g = 0; g < 4; g++) {
                uint32_t r0, r1, r2, r3;
                ldm_x4(r0, r1, r2, r3, smem_u32(&Kf[g * 16 + lr][kb + lc]));
                kf[2*g][0] = r0; kf[2*g+1][0] = r1; kf[2*g][1] = r2; kf[2*g+1][1] = r3;
            }
            #pragma unroll
            for (int nt = 0; nt < 8; nt++)
                mma_f16(sc[nt], qf[ks], kf[nt]);
        }

        // ---- pack half0 ----
        uint32_t pf0[4][4];
        #pragma unroll
        for (int nt = 0; nt < 8; nt++) {
            const uint32_t w0 = (nt < 4) ? m0[0] : m0[1];
            const uint32_t w1 = (nt < 4) ? m1[0] : m1[1];
            const int bp = (nt & 3) * 8 + tig * 2;
            pf0[nt >> 1][(nt & 1) * 2]     = h2exp2(packh2(sc[nt][0], sc[nt][1])) & mask2(w0, bp);
            pf0[nt >> 1][(nt & 1) * 2 + 1] = h2exp2(packh2(sc[nt][2], sc[nt][3])) & mask2(w1, bp);
        }

        // ---- QK half1 (keys 64..127) -- independent of pack0/PV0, fills tensor pipe ----
        float sc1[8][4];
        #pragma unroll
        for (int nt = 0; nt < 8; nt++)
            #pragma unroll
            for (int e = 0; e < 4; e++) sc1[nt][e] = 0.f;
        #pragma unroll
        for (int ks = 0; ks < 4; ks++) {
            const int kb = ks * 16;
            uint32_t kf[8][2];
            #pragma unroll
            for (int g = 0; g < 4; g++) {
                uint32_t r0, r1, r2, r3;
                ldm_x4(r0, r1, r2, r3, smem_u32(&Kf[64 + g * 16 + lr][kb + lc]));
                kf[2*g][0] = r0; kf[2*g+1][0] = r1; kf[2*g][1] = r2; kf[2*g+1][1] = r3;
            }
            #pragma unroll
            for (int nt = 0; nt < 8; nt++)
                mma_f16(sc1[nt], qf[ks], kf[nt]);
        }

        // ---- PV half0 + rowsum ----
        #pragma unroll
        for (int kp = 0; kp < 4; kp++) {
            mma_f16(rsacc, pf0[kp], vones);
            const int krow = kp * 16 + vr;
            #pragma unroll
            for (int g = 0; g < 4; g++) {
                uint32_t vf[2][2];
                uint32_t r0, r1, r2, r3;
                ldm_x4_trans(r0, r1, r2, r3, smem_u32(&Vf[krow][g * 16 + vc]));
                vf[0][0] = r0; vf[1][0] = r1; vf[0][1] = r2; vf[1][1] = r3;
                mma_f16(oacc[2*g + 0], pf0[kp], vf[0]);
                mma_f16(oacc[2*g + 1], pf0[kp], vf[1]);
            }
        }

        // ---- pack half1 (overlaps PV0 tail) ----
        uint32_t pf1[4][4];
        #pragma unroll
        for (int nt = 0; nt < 8; nt++) {
            const uint32_t w0 = (nt < 4) ? m0[2] : m0[3];
            const uint32_t w1 = (nt < 4) ? m1[2] : m1[3];
            const int bp = (nt & 3) * 8 + tig * 2;
            pf1[nt >> 1][(nt & 1) * 2]     = h2exp2(packh2(sc1[nt][0], sc1[nt][1])) & mask2(w0, bp);
            pf1[nt >> 1][(nt & 1) * 2 + 1] = h2exp2(packh2(sc1[nt][2], sc1[nt][3])) & mask2(w1, bp);
        }

        // ---- PV half1 + rowsum ----
        #pragma unroll
        for (int kp = 0; kp < 4; kp++) {
            mma_f16(rsacc, pf1[kp], vones);
            const int krow = 64 + kp * 16 + vr;
            #pragma unroll
            for (int g = 0; g < 4; g++) {
                uint32_t vf[2][2];
                uint32_t r0, r1, r2, r3;
                ldm_x4_trans(r0, r1, r2, r3, smem_u32(&Vf[krow][g * 16 + vc]));
                vf[0][0] = r0; vf[1][0] = r1; vf[0][1] = r2; vf[1][1] = r3;
                mma_f16(oacc[2*g + 0], pf1[kp], vf[0]);
                mma_f16(oacc[2*g + 1], pf1[kp], vf[1]);
            }
        }
    }

    // ---- epilogue: normalize, write split-bf16 merged [B,S,H*HS] ----
    const float inv0 = 1.f / rsacc[0], inv1 = 1.f / rsacc[2];
    const size_t orow0 = (size_t)(b * SEQ + q0 + w * 16 + gid) * D_MODEL + h * HS;
    const size_t orow1 = orow0 + 8 * D_MODEL;
    #pragma unroll
    for (int nt = 0; nt < 8; nt++) {
        const int c = nt * 8 + tig * 2;
        uint32_t hh, ll;
        split2pack(oacc[nt][0] * inv0, oacc[nt][1] * inv0, hh, ll);
        *(uint32_t*)&oh_g[orow0 + c] = hh;
        *(uint32_t*)&ol_g[orow0 + c] = ll;
        split2pack(oacc[nt][2] * inv1, oacc[nt][3] * inv1, hh, ll);
        *(uint32_t*)&oh_g[orow1 + c] = hh;
        *(uint32_t*)&ol_g[orow1 + c] = ll;
    }
}

// ---------------- launch ----------------
extern "C" void kernel_launch(void* const* d_in, const int* in_sizes, int n_in,
                              void* d_out, int out_size)
{
    const float* queries = (const float*)d_in[0];
    const float* keys    = (const float*)d_in[1];
    const float* values  = (const float*)d_in[2];
    const int*   mask    = (const int*)d_in[3];
    const float* Wq = (const float*)d_in[4];  const float* bq = (const float*)d_in[5];
    const float* Wk = (const float*)d_in[6];  const float* bk = (const float*)d_in[7];
    const float* Wv = (const float*)d_in[8];  const float* bv = (const float*)d_in[9];
    const float* Wy = (const float*)d_in[10]; const float* by = (const float*)d_in[11];
    const float* bq2 = (const float*)d_in[12];
    const float* bk2 = (const float*)d_in[13];
    const float* bv2 = (const float*)d_in[14];
    const float* by2 = (const float*)d_in[15];
    float* out = (float*)d_out;

    __nv_bfloat16 *xh, *xl, *wh, *wl, *oh, *ol;
    __half* qkvf;
    uint32_t* mb;
    cudaGetSymbolAddress((void**)&xh, g_xh);   cudaGetSymbolAddress((void**)&xl, g_xl);
    cudaGetSymbolAddress((void**)&wh, g_wh);   cudaGetSymbolAddress((void**)&wl, g_wl);
    cudaGetSymbolAddress((void**)&oh, g_oh);   cudaGetSymbolAddress((void**)&ol, g_ol);
    cudaGetSymbolAddress((void**)&qkvf, g_qkvf);
    cudaGetSymbolAddress((void**)&mb, g_mbits);

    static int attr_set = 0;
    static cudaStream_t s2 = nullptr;
    static cudaEvent_t evFork = nullptr, evJoin = nullptr;
    if (!attr_set) {
        cudaFuncSetAttribute(qkv_gemm_kernel, cudaFuncAttributeMaxDynamicSharedMemorySize,
                             (int)sizeof(QSmem));
        cudaFuncSetAttribute(y_gemm_kernel, cudaFuncAttributeMaxDynamicSharedMemorySize,
                             (int)sizeof(QSmem));
        cudaFuncSetAttribute(attn_kernel, cudaFuncAttributeMaxDynamicSharedMemorySize,
                             AT_SMEM);
        if (cudaStreamCreateWithFlags(&s2, cudaStreamNonBlocking) != cudaSuccess) s2 = nullptr;
        if (s2) {
            if (cudaEventCreateWithFlags(&evFork, cudaEventDisableTiming) != cudaSuccess ||
                cudaEventCreateWithFlags(&evJoin, cudaEventDisableTiming) != cudaSuccess) {
                s2 = nullptr;
            }
        }
        attr_set = 1;
    }

    const int W4 = (int)(W_N / 4), A4 = (int)(ACT_N / 4);
    const bool fork = (s2 != nullptr);

    // ---- fork: persistent throttled mask bitpack coexists with QKV pipeline ----
    if (fork) {
        cudaEventRecord(evFork, 0);
        cudaStreamWaitEvent(s2, evFork, 0);
        maskbits_kernel<<<MB_CTAS, 256, 0, s2>>>(mask, mb);
        cudaEventRecord(evJoin, s2);
    } else {
        maskbits_kernel<<<MB_CTAS, 256>>>(mask, mb);
    }

    // ---- main stream: preconversion + fused QKV GEMM ----
    splitw4_kernel<<<dim3(W4 / 256, 4), 256>>>(Wq, Wk, Wv, Wy, wh, wl);
    splita3_kernel<<<dim3(A4 / 256, 3), 256>>>(queries, keys, values, xh, xl);

    dim3 qgrid(24, MROWS / 128);
    qkv_gemm_kernel<<<qgrid, 256, sizeof(QSmem)>>>(xh, xl, wh, wl,
                                                   bq, bq2, bk, bk2, bv, bv2, qkvf);

    // ---- join before attention (needs mask bits) ----
    if (fork) cudaStreamWaitEvent(0, evJoin, 0);

    dim3 agrid(SEQ / 128, NH, BATCH);
    attn_kernel<<<agrid, 256, AT_SMEM>>>(qkvf, mb, oh, ol);

    dim3 ygrid(D_MODEL / 128, MROWS / 128);
    y_gemm_kernel<<<ygrid, 256, sizeof(QSmem)>>>(oh, ol, wh + 3 * W_N, wl + 3 * W_N,
                                                 by, by2, out);
}

// round 16
// speedup vs baseline: 1.6085x; 1.4396x over previous
#include <cuda_runtime.h>
#include <cuda_bf16.h>
#include <cuda_fp16.h>
#include <cstdint>

#define D_MODEL 1024
#define NH      16
#define HS      64
#define BATCH   2
#define SEQ     2048
#define MROWS   (BATCH*SEQ)   // 4096
#define ACT_N   ((size_t)MROWS*D_MODEL)   // 4M
#define W_N     ((size_t)D_MODEL*D_MODEL) // 1M
#define MWORDS  ((size_t)BATCH*NH*SEQ*SEQ/32)  // 4,194,304
#define QSCALE  0.18033688011112042f   // 0.125 * log2(e)

// ---------------- scratch (no allocations allowed) ----------------
__device__ __half g_xf[3][ACT_N];     // fp16 activations
__device__ __half g_wf[4][W_N];       // fp16 weights
__device__ __half g_qkvf[3][ACT_N];   // q/k/v head-split [B,H,S,HS] fp16 (q pre-scaled)
__device__ __half g_of[ACT_N];        // attn out fp16, merged [B,S,H*HS]
__device__ uint32_t g_mbits[MWORDS];

// ---------------- helpers ----------------
__device__ __forceinline__ uint32_t smem_u32(const void* p) {
    return (uint32_t)__cvta_generic_to_shared(p);
}
__device__ __forceinline__ void ldm_x4(uint32_t& r0, uint32_t& r1, uint32_t& r2, uint32_t& r3,
                                       uint32_t addr) {
    asm volatile("ldmatrix.sync.aligned.m8n8.x4.shared.b16 {%0,%1,%2,%3}, [%4];\n"
                 : "=r"(r0), "=r"(r1), "=r"(r2), "=r"(r3) : "r"(addr));
}
__device__ __forceinline__ void ldm_x4_trans(uint32_t& r0, uint32_t& r1, uint32_t& r2, uint32_t& r3,
                                             uint32_t addr) {
    asm volatile("ldmatrix.sync.aligned.m8n8.x4.trans.shared.b16 {%0,%1,%2,%3}, [%4];\n"
                 : "=r"(r0), "=r"(r1), "=r"(r2), "=r"(r3) : "r"(addr));
}
__device__ __forceinline__ void mma_f16(float* c, const uint32_t* a, const uint32_t* b) {
    asm volatile("mma.sync.aligned.m16n8k16.row.col.f32.f16.f16.f32 "
                 "{%0,%1,%2,%3}, {%4,%5,%6,%7}, {%8,%9}, {%0,%1,%2,%3};\n"
                 : "+f"(c[0]), "+f"(c[1]), "+f"(c[2]), "+f"(c[3])
                 : "r"(a[0]), "r"(a[1]), "r"(a[2]), "r"(a[3]), "r"(b[0]), "r"(b[1]));
}
__device__ __forceinline__ uint32_t packh2(float x0, float x1) {
    __half2 h = __floats2half2_rn(x0, x1);
    return *(uint32_t*)&h;
}
__device__ __forceinline__ uint32_t h2exp2(uint32_t x) {
    uint32_t r;
    asm("ex2.approx.f16x2 %0, %1;" : "=r"(r) : "r"(x));
    return r;
}
__device__ __forceinline__ uint32_t mask2(uint32_t w, int bp) {
    return (((w >> bp) & 1u) ? 0x0000FFFFu : 0u) |
           (((w >> (bp + 1)) & 1u) ? 0xFFFF0000u : 0u);
}
__device__ __forceinline__ void cp16(uint32_t dst, const void* src) {
    asm volatile("cp.async.cg.shared.global [%0], [%1], 16;\n" :: "r"(dst), "l"(src));
}
#define CP_COMMIT asm volatile("cp.async.commit_group;\n")
#define CP_WAIT0  asm volatile("cp.async.wait_group 0;\n" ::: "memory")
#define CP_WAIT1  asm volatile("cp.async.wait_group 1;\n" ::: "memory")

// ---------------- mask -> bitmask: persistent, throttled ----------------
#define MB_CTAS  128
#define MB_WPI   8

__global__ void __launch_bounds__(256)
maskbits_kernel(const int* __restrict__ mask, uint32_t* __restrict__ bits)
{
    const int gw = blockIdx.x * 8 + (threadIdx.x >> 5);
    const int nw = MB_CTAS * 8;
    const int lane = threadIdx.x & 31;
    for (size_t w0 = (size_t)gw * MB_WPI; w0 < MWORDS; w0 += (size_t)nw * MB_WPI) {
        int m[MB_WPI];
        #pragma unroll
        for (int j = 0; j < MB_WPI; j++)
            m[j] = mask[(w0 + j) * 32 + lane];
        #pragma unroll
        for (int j = 0; j < MB_WPI; j++) {
            uint32_t b = __ballot_sync(0xffffffff, m[j] != 0);
            if (lane == 0) bits[w0 + j] = b;
        }
    }
}

// ---------------- fp32 -> fp16 preconversion ----------------
__global__ void __launch_bounds__(256)
cvtw4_kernel(const float* __restrict__ w0, const float* __restrict__ w1,
             const float* __restrict__ w2, const float* __restrict__ w3,
             __half* __restrict__ out)
{
    const int y = blockIdx.y;
    const float* in = (y == 0) ? w0 : (y == 1) ? w1 : (y == 2) ? w2 : w3;
    size_t i = (size_t)blockIdx.x * 256 + threadIdx.x;
    float4 v = ((const float4*)in)[i];
    uint2 o;
    o.x = packh2(v.x, v.y);
    o.y = packh2(v.z, v.w);
    ((uint2*)(out + (size_t)y * W_N))[i] = o;
}
__global__ void __launch_bounds__(256)
cvta3_kernel(const float* __restrict__ a0, const float* __restrict__ a1,
             const float* __restrict__ a2, __half* __restrict__ out)
{
    const int y = blockIdx.y;
    const float* in = (y == 0) ? a0 : (y == 1) ? a1 : a2;
    size_t i = (size_t)blockIdx.x * 256 + threadIdx.x;
    float4 v = ((const float4*)in)[i];
    uint2 o;
    o.x = packh2(v.x, v.y);
    o.y = packh2(v.z, v.w);
    ((uint2*)(out + (size_t)y * ACT_N))[i] = o;
}

// ================= fp16 single-MMA GEMM core =================
#define GSTR 40   // 32 + 8 pad (half elems) -> conflict-free ldmatrix

struct GS16 {
    __half Af[2][128][GSTR];
    __half Wf[2][128][GSTR];
};  // 40960 B

// Fused QKV: grid (24, 32), wsel = bx>>3. fp16 head-split out, Q scaled.
__global__ void __launch_bounds__(256, 2)
qkv_gemm_kernel(const __half* __restrict__ xf_g, const __half* __restrict__ wf_g,
                const float* __restrict__ b1q, const float* __restrict__ b2q,
                const float* __restrict__ b1k, const float* __restrict__ b2k,
                const float* __restrict__ b1v, const float* __restrict__ b2v,
                __half* __restrict__ out_g)
{
    extern __shared__ char smem_raw[];
    GS16* S = (GS16*)smem_raw;

    const int wsel = blockIdx.x >> 3;
    const int m0 = blockIdx.y * 128, n0 = (blockIdx.x & 7) * 128;
    const int tid = threadIdx.x;
    const int w = tid >> 5, lane = tid & 31;
    const int wm = w & 1, wn = w >> 1;
    const int rm = wm * 64, rn = wn * 32;
    const int lr = lane & 15, lc = (lane >> 4) << 3;
    const int tig = lane & 3, gid = lane >> 2;

    const __half* srcA = xf_g + (size_t)wsel * ACT_N + (size_t)m0 * D_MODEL;
    const __half* srcW = wf_g + (size_t)wsel * W_N + (size_t)n0 * D_MODEL;
    const float* b1 = (wsel == 0) ? b1q : (wsel == 1) ? b1k : b1v;
    const float* b2 = (wsel == 0) ? b2q : (wsel == 1) ? b2k : b2v;
    const float scale = (wsel == 0) ? QSCALE : 1.f;
    __half* oH = out_g + (size_t)wsel * ACT_N;

    float cf[4][4][4];
    #pragma unroll
    for (int mi = 0; mi < 4; mi++)
        #pragma unroll
        for (int ni = 0; ni < 4; ni++)
            #pragma unroll
            for (int e = 0; e < 4; e++) cf[mi][ni][e] = 0.f;

    auto stage = [&](int kt, int buf) {
        const int kofs = kt * 32;
        #pragma unroll
        for (int i = 0; i < 4; i++) {
            int idx = tid + i * 256;           // 0..1023
            int arr = idx >> 9;                // 0=A 1=W
            int rem = idx & 511;
            int r = rem >> 2, c = (rem & 3) << 3;
            const __half* src = (arr ? srcW : srcA) + (size_t)r * D_MODEL + kofs + c;
            uint32_t dst = smem_u32(arr ? (void*)&S->Wf[buf][r][c] : (void*)&S->Af[buf][r][c]);
            cp16(dst, src);
        }
        CP_COMMIT;
    };

    stage(0, 0);
    stage(1, 1);

    const int NKT = D_MODEL / 32;
    for (int kt = 0; kt < NKT; kt++) {
        const int buf = kt & 1;
        if (kt + 1 < NKT) { CP_WAIT1; } else { CP_WAIT0; }
        __syncthreads();

        #pragma unroll
        for (int ks = 0; ks < 2; ks++) {
            const int kb = ks * 16;
            uint32_t af[4][4];
            #pragma unroll
            for (int mi = 0; mi < 4; mi++)
                ldm_x4(af[mi][0], af[mi][1], af[mi][2], af[mi][3],
                       smem_u32(&S->Af[buf][rm + mi * 16 + lr][kb + lc]));
            uint32_t bf[4][2];
            #pragma unroll
            for (int g = 0; g < 2; g++) {
                uint32_t r0, r1, r2, r3;
                ldm_x4(r0, r1, r2, r3, smem_u32(&S->Wf[buf][rn + g * 16 + lr][kb + lc]));
                bf[2*g][0] = r0; bf[2*g+1][0] = r1; bf[2*g][1] = r2; bf[2*g+1][1] = r3;
            }
            #pragma unroll
            for (int mi = 0; mi < 4; mi++)
                #pragma unroll
                for (int ni = 0; ni < 4; ni++)
                    mma_f16(cf[mi][ni], af[mi], bf[ni]);
        }
        __syncthreads();
        if (kt + 2 < NKT) stage(kt + 2, buf);
    }

    #pragma unroll
    for (int ni = 0; ni < 4; ni++) {
        const int c0 = rn + ni * 8 + tig * 2 + n0;
        const float bias0 = b1[c0] + b2[c0];
        const float bias1 = b1[c0 + 1] + b2[c0 + 1];
        #pragma unroll
        for (int mi = 0; mi < 4; mi++) {
            #pragma unroll
            for (int half = 0; half < 2; half++) {
                int m = m0 + rm + mi * 16 + gid + half * 8;
                float v0 = (cf[mi][ni][half * 2]     + bias0) * scale;
                float v1 = (cf[mi][ni][half * 2 + 1] + bias1) * scale;
                int bb = m >> 11, s = m & (SEQ - 1);
                int hh = c0 >> 6, d = c0 & (HS - 1);
                size_t off = (((size_t)(bb * NH + hh)) * SEQ + s) * HS + d;
                *(uint32_t*)&oH[off] = packh2(v0, v1);
            }
        }
    }
}

// Y GEMM: fp16 A (attn out) x fp16 Wy + bias -> fp32 out
__global__ void __launch_bounds__(256, 2)
y_gemm_kernel(const __half* __restrict__ Afg, const __half* __restrict__ Wfg,
              const float* __restrict__ b1, const float* __restrict__ b2,
              float* __restrict__ outF)
{
    extern __shared__ char smem_raw[];
    GS16* S = (GS16*)smem_raw;

    const int m0 = blockIdx.y * 128, n0 = blockIdx.x * 128;
    const int tid = threadIdx.x;
    const int w = tid >> 5, lane = tid & 31;
    const int wm = w & 1, wn = w >> 1;
    const int rm = wm * 64, rn = wn * 32;
    const int lr = lane & 15, lc = (lane >> 4) << 3;
    const int tig = lane & 3, gid = lane >> 2;

    const __half* srcA = Afg + (size_t)m0 * D_MODEL;
    const __half* srcW = Wfg + (size_t)n0 * D_MODEL;

    float cf[4][4][4];
    #pragma unroll
    for (int mi = 0; mi < 4; mi++)
        #pragma unroll
        for (int ni = 0; ni < 4; ni++)
            #pragma unroll
            for (int e = 0; e < 4; e++) cf[mi][ni][e] = 0.f;

    auto stage = [&](int kt, int buf) {
        const int kofs = kt * 32;
        #pragma unroll
        for (int i = 0; i < 4; i++) {
            int idx = tid + i * 256;
            int arr = idx >> 9;
            int rem = idx & 511;
            int r = rem >> 2, c = (rem & 3) << 3;
            const __half* src = (arr ? srcW : srcA) + (size_t)r * D_MODEL + kofs + c;
            uint32_t dst = smem_u32(arr ? (void*)&S->Wf[buf][r][c] : (void*)&S->Af[buf][r][c]);
            cp16(dst, src);
        }
        CP_COMMIT;
    };

    stage(0, 0);
    stage(1, 1);

    const int NKT = D_MODEL / 32;
    for (int kt = 0; kt < NKT; kt++) {
        const int buf = kt & 1;
        if (kt + 1 < NKT) { CP_WAIT1; } else { CP_WAIT0; }
        __syncthreads();

        #pragma unroll
        for (int ks = 0; ks < 2; ks++) {
            const int kb = ks * 16;
            uint32_t af[4][4];
            #pragma unroll
            for (int mi = 0; mi < 4; mi++)
                ldm_x4(af[mi][0], af[mi][1], af[mi][2], af[mi][3],
                       smem_u32(&S->Af[buf][rm + mi * 16 + lr][kb + lc]));
            uint32_t bf[4][2];
            #pragma unroll
            for (int g = 0; g < 2; g++) {
                uint32_t r0, r1, r2, r3;
                ldm_x4(r0, r1, r2, r3, smem_u32(&S->Wf[buf][rn + g * 16 + lr][kb + lc]));
                bf[2*g][0] = r0; bf[2*g+1][0] = r1; bf[2*g][1] = r2; bf[2*g+1][1] = r3;
            }
            #pragma unroll
            for (int mi = 0; mi < 4; mi++)
                #pragma unroll
                for (int ni = 0; ni < 4; ni++)
                    mma_f16(cf[mi][ni], af[mi], bf[ni]);
        }
        __syncthreads();
        if (kt + 2 < NKT) stage(kt + 2, buf);
    }

    #pragma unroll
    for (int ni = 0; ni < 4; ni++) {
        const int c0 = n0 + rn + ni * 8 + tig * 2;
        const float bias0 = b1[c0] + b2[c0];
        const float bias1 = b1[c0 + 1] + b2[c0 + 1];
        #pragma unroll
        for (int mi = 0; mi < 4; mi++) {
            #pragma unroll
            for (int half = 0; half < 2; half++) {
                int m = m0 + rm + mi * 16 + gid + half * 8;
                *(float2*)&outF[(size_t)m * D_MODEL + c0] =
                    make_float2(cf[mi][ni][half * 2] + bias0, cf[mi][ni][half * 2 + 1] + bias1);
            }
        }
    }
}

// ================= Attention (R15 structure, fp16 output) =================
#define AT_SMEM (2*2*128*72*2)   // 73728 B -> 2 CTAs/SM

__global__ void __launch_bounds__(256, 2)
attn_kernel(const __half* __restrict__ qkv_g, const uint32_t* __restrict__ mbits,
            __half* __restrict__ of_g)
{
    extern __shared__ char smem_raw[];
    typedef __half KVbuf[2][128][72];
    KVbuf* KV = (KVbuf*)smem_raw;

    const int tid = threadIdx.x;
    const int h = blockIdx.y, b = blockIdx.z;
    const int bh = b * NH + h;
    const int q0 = blockIdx.x * 128;
    const int w = tid >> 5, lane = tid & 31;
    const int lr = lane & 15, lc = (lane >> 4) << 3;
    const int tig = lane & 3, gid = lane >> 2;
    const int vr = ((lane >> 4) << 3) + (lane & 7), vc = lane & 8;

    const __half* qf_g = qkv_g;
    const __half* kf_g = qkv_g + ACT_N;
    const __half* vf_g = qkv_g + 2 * ACT_N;
    const size_t kvbase = (size_t)bh * SEQ * HS;

    {
        __half (*Qs)[72] = (__half (*)[72])&KV[0][0][0][0];
        #pragma unroll
        for (int j = 0; j < 4; j++) {
            int idx = tid + j * 256;
            int r = idx >> 3, c = (idx & 7) << 3;
            cp16(smem_u32(&Qs[r][c]), qf_g + kvbase + (size_t)(q0 + r) * HS + c);
        }
        CP_COMMIT; CP_WAIT0;
        __syncthreads();
    }
    uint32_t qf[4][4];
    {
        __half (*Qs)[72] = (__half (*)[72])&KV[0][0][0][0];
        #pragma unroll
        for (int ks = 0; ks < 4; ks++)
            ldm_x4(qf[ks][0], qf[ks][1], qf[ks][2], qf[ks][3],
                   smem_u32(&Qs[w * 16 + lr][ks * 16 + lc]));
        __syncthreads();
    }

    float oacc[8][4];
    #pragma unroll
    for (int nt = 0; nt < 8; nt++)
        #pragma unroll
        for (int e = 0; e < 4; e++) oacc[nt][e] = 0.f;
    float rsacc[4] = {0.f, 0.f, 0.f, 0.f};

    const uint32_t* mrow0 = mbits + ((size_t)(bh * SEQ) + q0 + w * 16 + gid) * 64;
    const uint32_t* mrow1 = mrow0 + 8 * 64;

    auto stage_kv = [&](int t, int buf) {
        #pragma unroll
        for (int j = 0; j < 8; j++) {
            int idx = tid + j * 256;
            int a = idx >> 10, rem = idx & 1023;
            int r = rem >> 3, c = (rem & 7) << 3;
            const __half* src = (a ? vf_g : kf_g) + kvbase + (size_t)(t * 128 + r) * HS + c;
            cp16(smem_u32(&KV[buf][a][r][c]), src);
        }
        CP_COMMIT;
    };

    stage_kv(0, 0);

    const uint32_t vones[2] = {0x3C003C00u, 0x3C003C00u};
    const int NT = SEQ / 128;   // 16

    for (int t = 0; t < NT; t++) {
        CP_WAIT0;
        __syncthreads();
        if (t + 1 < NT) stage_kv(t + 1, (t + 1) & 1);

        const __half (*Kf)[72] = KV[t & 1][0];
        const __half (*Vf)[72] = KV[t & 1][1];

        uint32_t m0[4], m1[4];
        #pragma unroll
        for (int j = 0; j < 4; j++) { m0[j] = mrow0[t * 4 + j]; m1[j] = mrow1[t * 4 + j]; }

        // ---- QK half0 ----
        float sc[8][4];
        #pragma unroll
        for (int nt = 0; nt < 8; nt++)
            #pragma unroll
            for (int e = 0; e < 4; e++) sc[nt][e] = 0.f;
        #pragma unroll
        for (int ks = 0; ks < 4; ks++) {
            const int kb = ks * 16;
            uint32_t kf[8][2];
            #pragma unroll
            for (int g = 0; g < 4; g++) {
                uint32_t r0, r1, r2, r3;
                ldm_x4(r0, r1, r2, r3, smem_u32(&Kf[g * 16 + lr][kb + lc]));
                kf[2*g][0] = r0; kf[2*g+1][0] = r1; kf[2*g][1] = r2; kf[2*g+1][1] = r3;
            }
            #pragma unroll
            for (int nt = 0; nt < 8; nt++)
                mma_f16(sc[nt], qf[ks], kf[nt]);
        }

        // ---- pack half0 ----
        uint32_t pf0[4][4];
        #pragma unroll
        for (int nt = 0; nt < 8; nt++) {
            const uint32_t w0 = (nt < 4) ? m0[0] : m0[1];
            const uint32_t w1 = (nt < 4) ? m1[0] : m1[1];
            const int bp = (nt & 3) * 8 + tig * 2;
            pf0[nt >> 1][(nt & 1) * 2]     = h2exp2(packh2(sc[nt][0], sc[nt][1])) & mask2(w0, bp);
            pf0[nt >> 1][(nt & 1) * 2 + 1] = h2exp2(packh2(sc[nt][2], sc[nt][3])) & mask2(w1, bp);
        }

        // ---- QK half1 ----
        float sc1[8][4];
        #pragma unroll
        for (int nt = 0; nt < 8; nt++)
            #pragma unroll
            for (int e = 0; e < 4; e++) sc1[nt][e] = 0.f;
        #pragma unroll
        for (int ks = 0; ks < 4; ks++) {
            const int kb = ks * 16;
            uint32_t kf[8][2];
            #pragma unroll
            for (int g = 0; g < 4; g++) {
                uint32_t r0, r1, r2, r3;
                ldm_x4(r0, r1, r2, r3, smem_u32(&Kf[64 + g * 16 + lr][kb + lc]));
                kf[2*g][0] = r0; kf[2*g+1][0] = r1; kf[2*g][1] = r2; kf[2*g+1][1] = r3;
            }
            #pragma unroll
            for (int nt = 0; nt < 8; nt++)
                mma_f16(sc1[nt], qf[ks], kf[nt]);
        }

        // ---- PV half0 + rowsum ----
        #pragma unroll
        for (int kp = 0; kp < 4; kp++) {
            mma_f16(rsacc, pf0[kp], vones);
            const int krow = kp * 16 + vr;
            #pragma unroll
            for (int g = 0; g < 4; g++) {
                uint32_t vf[2][2];
                uint32_t r0, r1, r2, r3;
                ldm_x4_trans(r0, r1, r2, r3, smem_u32(&Vf[krow][g * 16 + vc]));
                vf[0][0] = r0; vf[1][0] = r1; vf[0][1] = r2; vf[1][1] = r3;
                mma_f16(oacc[2*g + 0], pf0[kp], vf[0]);
                mma_f16(oacc[2*g + 1], pf0[kp], vf[1]);
            }
        }

        // ---- pack half1 ----
        uint32_t pf1[4][4];
        #pragma unroll
        for (int nt = 0; nt < 8; nt++) {
            const uint32_t w0 = (nt < 4) ? m0[2] : m0[3];
            const uint32_t w1 = (nt < 4) ? m1[2] : m1[3];
            const int bp = (nt & 3) * 8 + tig * 2;
            pf1[nt >> 1][(nt & 1) * 2]     = h2exp2(packh2(sc1[nt][0], sc1[nt][1])) & mask2(w0, bp);
            pf1[nt >> 1][(nt & 1) * 2 + 1] = h2exp2(packh2(sc1[nt][2], sc1[nt][3])) & mask2(w1, bp);
        }

        // ---- PV half1 + rowsum ----
        #pragma unroll
        for (int kp = 0; kp < 4; kp++) {
            mma_f16(rsacc, pf1[kp], vones);
            const int krow = 64 + kp * 16 + vr;
            #pragma unroll
            for (int g = 0; g < 4; g++) {
                uint32_t vf[2][2];
                uint32_t r0, r1, r2, r3;
                ldm_x4_trans(r0, r1, r2, r3, smem_u32(&Vf[krow][g * 16 + vc]));
                vf[0][0] = r0; vf[1][0] = r1; vf[0][1] = r2; vf[1][1] = r3;
                mma_f16(oacc[2*g + 0], pf1[kp], vf[0]);
                mma_f16(oacc[2*g + 1], pf1[kp], vf[1]);
            }
        }
    }

    // ---- epilogue: normalize, write fp16 merged [B,S,H*HS] ----
    const float inv0 = 1.f / rsacc[0], inv1 = 1.f / rsacc[2];
    const size_t orow0 = (size_t)(b * SEQ + q0 + w * 16 + gid) * D_MODEL + h * HS;
    const size_t orow1 = orow0 + 8 * D_MODEL;
    #pragma unroll
    for (int nt = 0; nt < 8; nt++) {
        const int c = nt * 8 + tig * 2;
        *(uint32_t*)&of_g[orow0 + c] = packh2(oacc[nt][0] * inv0, oacc[nt][1] * inv0);
        *(uint32_t*)&of_g[orow1 + c] = packh2(oacc[nt][2] * inv1, oacc[nt][3] * inv1);
    }
}

// ---------------- launch ----------------
extern "C" void kernel_launch(void* const* d_in, const int* in_sizes, int n_in,
                              void* d_out, int out_size)
{
    const float* queries = (const float*)d_in[0];
    const float* keys    = (const float*)d_in[1];
    const float* values  = (const float*)d_in[2];
    const int*   mask    = (const int*)d_in[3];
    const float* Wq = (const float*)d_in[4];  const float* bq = (const float*)d_in[5];
    const float* Wk = (const float*)d_in[6];  const float* bk = (const float*)d_in[7];
    const float* Wv = (const float*)d_in[8];  const float* bv = (const float*)d_in[9];
    const float* Wy = (const float*)d_in[10]; const float* by = (const float*)d_in[11];
    const float* bq2 = (const float*)d_in[12];
    const float* bk2 = (const float*)d_in[13];
    const float* bv2 = (const float*)d_in[14];
    const float* by2 = (const float*)d_in[15];
    float* out = (float*)d_out;

    __half *xf, *wf, *qkvf, *of;
    uint32_t* mb;
    cudaGetSymbolAddress((void**)&xf, g_xf);
    cudaGetSymbolAddress((void**)&wf, g_wf);
    cudaGetSymbolAddress((void**)&qkvf, g_qkvf);
    cudaGetSymbolAddress((void**)&of, g_of);
    cudaGetSymbolAddress((void**)&mb, g_mbits);

    static int attr_set = 0;
    static cudaStream_t s2 = nullptr;
    static cudaEvent_t evFork = nullptr, evJoin = nullptr;
    if (!attr_set) {
        cudaFuncSetAttribute(qkv_gemm_kernel, cudaFuncAttributeMaxDynamicSharedMemorySize,
                             (int)sizeof(GS16));
        cudaFuncSetAttribute(y_gemm_kernel, cudaFuncAttributeMaxDynamicSharedMemorySize,
                             (int)sizeof(GS16));
        cudaFuncSetAttribute(attn_kernel, cudaFuncAttributeMaxDynamicSharedMemorySize,
                             AT_SMEM);
        if (cudaStreamCreateWithFlags(&s2, cudaStreamNonBlocking) != cudaSuccess) s2 = nullptr;
        if (s2) {
            if (cudaEventCreateWithFlags(&evFork, cudaEventDisableTiming) != cudaSuccess ||
                cudaEventCreateWithFlags(&evJoin, cudaEventDisableTiming) != cudaSuccess) {
                s2 = nullptr;
            }
        }
        attr_set = 1;
    }

    const int W4 = (int)(W_N / 4), A4 = (int)(ACT_N / 4);
    const bool fork = (s2 != nullptr);

    // ---- fork: persistent throttled mask bitpack coexists with QKV pipeline ----
    if (fork) {
        cudaEventRecord(evFork, 0);
        cudaStreamWaitEvent(s2, evFork, 0);
        maskbits_kernel<<<MB_CTAS, 256, 0, s2>>>(mask, mb);
        cudaEventRecord(evJoin, s2);
    } else {
        maskbits_kernel<<<MB_CTAS, 256>>>(mask, mb);
    }

    // ---- main stream: fp16 preconversion + fused QKV GEMM ----
    cvtw4_kernel<<<dim3(W4 / 256, 4), 256>>>(Wq, Wk, Wv, Wy, wf);
    cvta3_kernel<<<dim3(A4 / 256, 3), 256>>>(queries, keys, values, xf);

    dim3 qgrid(24, MROWS / 128);
    qkv_gemm_kernel<<<qgrid, 256, sizeof(GS16)>>>(xf, wf,
                                                  bq, bq2, bk, bk2, bv, bv2, qkvf);

    // ---- join before attention (needs mask bits) ----
    if (fork) cudaStreamWaitEvent(0, evJoin, 0);

    dim3 agrid(SEQ / 128, NH, BATCH);
    attn_kernel<<<agrid, 256, AT_SMEM>>>(qkvf, mb, of);

    dim3 ygrid(D_MODEL / 128, MROWS / 128);
    y_gemm_kernel<<<ygrid, 256, sizeof(GS16)>>>(of, wf + 3 * W_N, by, by2, out);
}

// round 17
// speedup vs baseline: 1.6507x; 1.0262x over previous
#include <cuda_runtime.h>
#include <cuda_bf16.h>
#include <cuda_fp16.h>
#include <cstdint>

#define D_MODEL 1024
#define NH      16
#define HS      64
#define BATCH   2
#define SEQ     2048
#define MROWS   (BATCH*SEQ)   // 4096
#define ACT_N   ((size_t)MROWS*D_MODEL)   // 4M
#define W_N     ((size_t)D_MODEL*D_MODEL) // 1M
#define MWORDS  ((size_t)BATCH*NH*SEQ*SEQ/32)  // 4,194,304
#define QSCALE  0.18033688011112042f   // 0.125 * log2(e)

// ---------------- scratch (no allocations allowed) ----------------
__device__ __half g_xf[3][ACT_N];     // fp16 activations
__device__ __half g_wf[4][W_N];       // fp16 weights
__device__ __half g_qkvf[3][ACT_N];   // q/k/v head-split [B,H,S,HS] fp16 (q pre-scaled)
__device__ __half g_of[ACT_N];        // attn out fp16, merged [B,S,H*HS]
__device__ uint32_t g_mbits[MWORDS];

// ---------------- helpers ----------------
__device__ __forceinline__ uint32_t smem_u32(const void* p) {
    return (uint32_t)__cvta_generic_to_shared(p);
}
__device__ __forceinline__ void ldm_x4(uint32_t& r0, uint32_t& r1, uint32_t& r2, uint32_t& r3,
                                       uint32_t addr) {
    asm volatile("ldmatrix.sync.aligned.m8n8.x4.shared.b16 {%0,%1,%2,%3}, [%4];\n"
                 : "=r"(r0), "=r"(r1), "=r"(r2), "=r"(r3) : "r"(addr));
}
__device__ __forceinline__ void ldm_x4_trans(uint32_t& r0, uint32_t& r1, uint32_t& r2, uint32_t& r3,
                                             uint32_t addr) {
    asm volatile("ldmatrix.sync.aligned.m8n8.x4.trans.shared.b16 {%0,%1,%2,%3}, [%4];\n"
                 : "=r"(r0), "=r"(r1), "=r"(r2), "=r"(r3) : "r"(addr));
}
__device__ __forceinline__ void mma_f16(float* c, const uint32_t* a, const uint32_t* b) {
    asm volatile("mma.sync.aligned.m16n8k16.row.col.f32.f16.f16.f32 "
                 "{%0,%1,%2,%3}, {%4,%5,%6,%7}, {%8,%9}, {%0,%1,%2,%3};\n"
                 : "+f"(c[0]), "+f"(c[1]), "+f"(c[2]), "+f"(c[3])
                 : "r"(a[0]), "r"(a[1]), "r"(a[2]), "r"(a[3]), "r"(b[0]), "r"(b[1]));
}
__device__ __forceinline__ uint32_t packh2(float x0, float x1) {
    __half2 h = __floats2half2_rn(x0, x1);
    return *(uint32_t*)&h;
}
__device__ __forceinline__ uint32_t h2exp2(uint32_t x) {
    uint32_t r;
    asm("ex2.approx.f16x2 %0, %1;" : "=r"(r) : "r"(x));
    return r;
}
__device__ __forceinline__ uint32_t mask2(uint32_t w, int bp) {
    return (((w >> bp) & 1u) ? 0x0000FFFFu : 0u) |
           (((w >> (bp + 1)) & 1u) ? 0xFFFF0000u : 0u);
}
__device__ __forceinline__ void cp16(uint32_t dst, const void* src) {
    asm volatile("cp.async.cg.shared.global [%0], [%1], 16;\n" :: "r"(dst), "l"(src));
}
#define CP_COMMIT asm volatile("cp.async.commit_group;\n")
#define CP_WAIT0  asm volatile("cp.async.wait_group 0;\n" ::: "memory")
#define CP_WAIT1  asm volatile("cp.async.wait_group 1;\n" ::: "memory")

// ---------------- mask -> bitmask: persistent, throttled ----------------
#define MB_CTAS  128
#define MB_WPI   8

__global__ void __launch_bounds__(256)
maskbits_kernel(const int* __restrict__ mask, uint32_t* __restrict__ bits)
{
    const int gw = blockIdx.x * 8 + (threadIdx.x >> 5);
    const int nw = MB_CTAS * 8;
    const int lane = threadIdx.x & 31;
    for (size_t w0 = (size_t)gw * MB_WPI; w0 < MWORDS; w0 += (size_t)nw * MB_WPI) {
        int m[MB_WPI];
        #pragma unroll
        for (int j = 0; j < MB_WPI; j++)
            m[j] = mask[(w0 + j) * 32 + lane];
        #pragma unroll
        for (int j = 0; j < MB_WPI; j++) {
            uint32_t b = __ballot_sync(0xffffffff, m[j] != 0);
            if (lane == 0) bits[w0 + j] = b;
        }
    }
}

// ---------------- fp32 -> fp16 preconversion ----------------
__global__ void __launch_bounds__(256)
cvtw4_kernel(const float* __restrict__ w0, const float* __restrict__ w1,
             const float* __restrict__ w2, const float* __restrict__ w3,
             __half* __restrict__ out)
{
    const int y = blockIdx.y;
    const float* in = (y == 0) ? w0 : (y == 1) ? w1 : (y == 2) ? w2 : w3;
    size_t i = (size_t)blockIdx.x * 256 + threadIdx.x;
    float4 v = ((const float4*)in)[i];
    uint2 o;
    o.x = packh2(v.x, v.y);
    o.y = packh2(v.z, v.w);
    ((uint2*)(out + (size_t)y * W_N))[i] = o;
}
__global__ void __launch_bounds__(256)
cvta3_kernel(const float* __restrict__ a0, const float* __restrict__ a1,
             const float* __restrict__ a2, __half* __restrict__ out)
{
    const int y = blockIdx.y;
    const float* in = (y == 0) ? a0 : (y == 1) ? a1 : a2;
    size_t i = (size_t)blockIdx.x * 256 + threadIdx.x;
    float4 v = ((const float4*)in)[i];
    uint2 o;
    o.x = packh2(v.x, v.y);
    o.y = packh2(v.z, v.w);
    ((uint2*)(out + (size_t)y * ACT_N))[i] = o;
}

// ================= fp16 single-MMA GEMM core, K-chunk 64 =================
#define GSTR 72   // 64 + 8 pad (half elems); 144B stride ≡ 16 mod 128 -> conflict-free

struct GS16 {
    __half Af[2][128][GSTR];
    __half Wf[2][128][GSTR];
};  // 73728 B

// Fused QKV: grid (24, 32), wsel = bx>>3. fp16 head-split out, Q scaled.
__global__ void __launch_bounds__(256, 2)
qkv_gemm_kernel(const __half* __restrict__ xf_g, const __half* __restrict__ wf_g,
                const float* __restrict__ b1q, const float* __restrict__ b2q,
                const float* __restrict__ b1k, const float* __restrict__ b2k,
                const float* __restrict__ b1v, const float* __restrict__ b2v,
                __half* __restrict__ out_g)
{
    extern __shared__ char smem_raw[];
    GS16* S = (GS16*)smem_raw;

    const int wsel = blockIdx.x >> 3;
    const int m0 = blockIdx.y * 128, n0 = (blockIdx.x & 7) * 128;
    const int tid = threadIdx.x;
    const int w = tid >> 5, lane = tid & 31;
    const int wm = w & 1, wn = w >> 1;
    const int rm = wm * 64, rn = wn * 32;
    const int lr = lane & 15, lc = (lane >> 4) << 3;
    const int tig = lane & 3, gid = lane >> 2;

    const __half* srcA = xf_g + (size_t)wsel * ACT_N + (size_t)m0 * D_MODEL;
    const __half* srcW = wf_g + (size_t)wsel * W_N + (size_t)n0 * D_MODEL;
    const float* b1 = (wsel == 0) ? b1q : (wsel == 1) ? b1k : b1v;
    const float* b2 = (wsel == 0) ? b2q : (wsel == 1) ? b2k : b2v;
    const float scale = (wsel == 0) ? QSCALE : 1.f;
    __half* oH = out_g + (size_t)wsel * ACT_N;

    float cf[4][4][4];
    #pragma unroll
    for (int mi = 0; mi < 4; mi++)
        #pragma unroll
        for (int ni = 0; ni < 4; ni++)
            #pragma unroll
            for (int e = 0; e < 4; e++) cf[mi][ni][e] = 0.f;

    // stage a 64-wide K-slab of A and W into buffer buf
    auto stage = [&](int kt, int buf) {
        const int kofs = kt * 64;
        #pragma unroll
        for (int i = 0; i < 8; i++) {
            int idx = tid + i * 256;           // 0..2047
            int arr = idx >> 10;               // 0=A 1=W
            int rem = idx & 1023;
            int r = rem >> 3, c = (rem & 7) << 3;
            const __half* src = (arr ? srcW : srcA) + (size_t)r * D_MODEL + kofs + c;
            uint32_t dst = smem_u32(arr ? (void*)&S->Wf[buf][r][c] : (void*)&S->Af[buf][r][c]);
            cp16(dst, src);
        }
        CP_COMMIT;
    };

    stage(0, 0);
    stage(1, 1);

    const int NKT = D_MODEL / 64;   // 16
    for (int kt = 0; kt < NKT; kt++) {
        const int buf = kt & 1;
        if (kt + 1 < NKT) { CP_WAIT1; } else { CP_WAIT0; }
        __syncthreads();

        #pragma unroll
        for (int ks = 0; ks < 4; ks++) {
            const int kb = ks * 16;
            uint32_t af[4][4];
            #pragma unroll
            for (int mi = 0; mi < 4; mi++)
                ldm_x4(af[mi][0], af[mi][1], af[mi][2], af[mi][3],
                       smem_u32(&S->Af[buf][rm + mi * 16 + lr][kb + lc]));
            uint32_t bf[4][2];
            #pragma unroll
            for (int g = 0; g < 2; g++) {
                uint32_t r0, r1, r2, r3;
                ldm_x4(r0, r1, r2, r3, smem_u32(&S->Wf[buf][rn + g * 16 + lr][kb + lc]));
                bf[2*g][0] = r0; bf[2*g+1][0] = r1; bf[2*g][1] = r2; bf[2*g+1][1] = r3;
            }
            #pragma unroll
            for (int mi = 0; mi < 4; mi++)
                #pragma unroll
                for (int ni = 0; ni < 4; ni++)
                    mma_f16(cf[mi][ni], af[mi], bf[ni]);
        }
        __syncthreads();
        if (kt + 2 < NKT) stage(kt + 2, buf);
    }

    #pragma unroll
    for (int ni = 0; ni < 4; ni++) {
        const int c0 = rn + ni * 8 + tig * 2 + n0;
        const float bias0 = b1[c0] + b2[c0];
        const float bias1 = b1[c0 + 1] + b2[c0 + 1];
        #pragma unroll
        for (int mi = 0; mi < 4; mi++) {
            #pragma unroll
            for (int half = 0; half < 2; half++) {
                int m = m0 + rm + mi * 16 + gid + half * 8;
                float v0 = (cf[mi][ni][half * 2]     + bias0) * scale;
                float v1 = (cf[mi][ni][half * 2 + 1] + bias1) * scale;
                int bb = m >> 11, s = m & (SEQ - 1);
                int hh = c0 >> 6, d = c0 & (HS - 1);
                size_t off = (((size_t)(bb * NH + hh)) * SEQ + s) * HS + d;
                *(uint32_t*)&oH[off] = packh2(v0, v1);
            }
        }
    }
}

// Y GEMM: fp16 A (attn out) x fp16 Wy + bias -> fp32 out
__global__ void __launch_bounds__(256, 2)
y_gemm_kernel(const __half* __restrict__ Afg, const __half* __restrict__ Wfg,
              const float* __restrict__ b1, const float* __restrict__ b2,
              float* __restrict__ outF)
{
    extern __shared__ char smem_raw[];
    GS16* S = (GS16*)smem_raw;

    const int m0 = blockIdx.y * 128, n0 = blockIdx.x * 128;
    const int tid = threadIdx.x;
    const int w = tid >> 5, lane = tid & 31;
    const int wm = w & 1, wn = w >> 1;
    const int rm = wm * 64, rn = wn * 32;
    const int lr = lane & 15, lc = (lane >> 4) << 3;
    const int tig = lane & 3, gid = lane >> 2;

    const __half* srcA = Afg + (size_t)m0 * D_MODEL;
    const __half* srcW = Wfg + (size_t)n0 * D_MODEL;

    float cf[4][4][4];
    #pragma unroll
    for (int mi = 0; mi < 4; mi++)
        #pragma unroll
        for (int ni = 0; ni < 4; ni++)
            #pragma unroll
            for (int e = 0; e < 4; e++) cf[mi][ni][e] = 0.f;

    auto stage = [&](int kt, int buf) {
        const int kofs = kt * 64;
        #pragma unroll
        for (int i = 0; i < 8; i++) {
            int idx = tid + i * 256;
            int arr = idx >> 10;
            int rem = idx & 1023;
            int r = rem >> 3, c = (rem & 7) << 3;
            const __half* src = (arr ? srcW : srcA) + (size_t)r * D_MODEL + kofs + c;
            uint32_t dst = smem_u32(arr ? (void*)&S->Wf[buf][r][c] : (void*)&S->Af[buf][r][c]);
            cp16(dst, src);
        }
        CP_COMMIT;
    };

    stage(0, 0);
    stage(1, 1);

    const int NKT = D_MODEL / 64;   // 16
    for (int kt = 0; kt < NKT; kt++) {
        const int buf = kt & 1;
        if (kt + 1 < NKT) { CP_WAIT1; } else { CP_WAIT0; }
        __syncthreads();

        #pragma unroll
        for (int ks = 0; ks < 4; ks++) {
            const int kb = ks * 16;
            uint32_t af[4][4];
            #pragma unroll
            for (int mi = 0; mi < 4; mi++)
                ldm_x4(af[mi][0], af[mi][1], af[mi][2], af[mi][3],
                       smem_u32(&S->Af[buf][rm + mi * 16 + lr][kb + lc]));
            uint32_t bf[4][2];
            #pragma unroll
            for (int g = 0; g < 2; g++) {
                uint32_t r0, r1, r2, r3;
                ldm_x4(r0, r1, r2, r3, smem_u32(&S->Wf[buf][rn + g * 16 + lr][kb + lc]));
                bf[2*g][0] = r0; bf[2*g+1][0] = r1; bf[2*g][1] = r2; bf[2*g+1][1] = r3;
            }
            #pragma unroll
            for (int mi = 0; mi < 4; mi++)
                #pragma unroll
                for (int ni = 0; ni < 4; ni++)
                    mma_f16(cf[mi][ni], af[mi], bf[ni]);
        }
        __syncthreads();
        if (kt + 2 < NKT) stage(kt + 2, buf);
    }

    #pragma unroll
    for (int ni = 0; ni < 4; ni++) {
        const int c0 = n0 + rn + ni * 8 + tig * 2;
        const float bias0 = b1[c0] + b2[c0];
        const float bias1 = b1[c0 + 1] + b2[c0 + 1];
        #pragma unroll
        for (int mi = 0; mi < 4; mi++) {
            #pragma unroll
            for (int half = 0; half < 2; half++) {
                int m = m0 + rm + mi * 16 + gid + half * 8;
                *(float2*)&outF[(size_t)m * D_MODEL + c0] =
                    make_float2(cf[mi][ni][half * 2] + bias0, cf[mi][ni][half * 2 + 1] + bias1);
            }
        }
    }
}

// ================= Attention (R16-proven, unchanged) =================
#define AT_SMEM (2*2*128*72*2)   // 73728 B -> 2 CTAs/SM

__global__ void __launch_bounds__(256, 2)
attn_kernel(const __half* __restrict__ qkv_g, const uint32_t* __restrict__ mbits,
            __half* __restrict__ of_g)
{
    extern __shared__ char smem_raw[];
    typedef __half KVbuf[2][128][72];
    KVbuf* KV = (KVbuf*)smem_raw;

    const int tid = threadIdx.x;
    const int h = blockIdx.y, b = blockIdx.z;
    const int bh = b * NH + h;
    const int q0 = blockIdx.x * 128;
    const int w = tid >> 5, lane = tid & 31;
    const int lr = lane & 15, lc = (lane >> 4) << 3;
    const int tig = lane & 3, gid = lane >> 2;
    const int vr = ((lane >> 4) << 3) + (lane & 7), vc = lane & 8;

    const __half* qf_g = qkv_g;
    const __half* kf_g = qkv_g + ACT_N;
    const __half* vf_g = qkv_g + 2 * ACT_N;
    const size_t kvbase = (size_t)bh * SEQ * HS;

    {
        __half (*Qs)[72] = (__half (*)[72])&KV[0][0][0][0];
        #pragma unroll
        for (int j = 0; j < 4; j++) {
            int idx = tid + j * 256;
            int r = idx >> 3, c = (idx & 7) << 3;
            cp16(smem_u32(&Qs[r][c]), qf_g + kvbase + (size_t)(q0 + r) * HS + c);
        }
        CP_COMMIT; CP_WAIT0;
        __syncthreads();
    }
    uint32_t qf[4][4];
    {
        __half (*Qs)[72] = (__half (*)[72])&KV[0][0][0][0];
        #pragma unroll
        for (int ks = 0; ks < 4; ks++)
            ldm_x4(qf[ks][0], qf[ks][1], qf[ks][2], qf[ks][3],
                   smem_u32(&Qs[w * 16 + lr][ks * 16 + lc]));
        __syncthreads();
    }

    float oacc[8][4];
    #pragma unroll
    for (int nt = 0; nt < 8; nt++)
        #pragma unroll
        for (int e = 0; e < 4; e++) oacc[nt][e] = 0.f;
    float rsacc[4] = {0.f, 0.f, 0.f, 0.f};

    const uint32_t* mrow0 = mbits + ((size_t)(bh * SEQ) + q0 + w * 16 + gid) * 64;
    const uint32_t* mrow1 = mrow0 + 8 * 64;

    auto stage_kv = [&](int t, int buf) {
        #pragma unroll
        for (int j = 0; j < 8; j++) {
            int idx = tid + j * 256;
            int a = idx >> 10, rem = idx & 1023;
            int r = rem >> 3, c = (rem & 7) << 3;
            const __half* src = (a ? vf_g : kf_g) + kvbase + (size_t)(t * 128 + r) * HS + c;
            cp16(smem_u32(&KV[buf][a][r][c]), src);
        }
        CP_COMMIT;
    };

    stage_kv(0, 0);

    const uint32_t vones[2] = {0x3C003C00u, 0x3C003C00u};
    const int NT = SEQ / 128;   // 16

    for (int t = 0; t < NT; t++) {
        CP_WAIT0;
        __syncthreads();
        if (t + 1 < NT) stage_kv(t + 1, (t + 1) & 1);

        const __half (*Kf)[72] = KV[t & 1][0];
        const __half (*Vf)[72] = KV[t & 1][1];

        uint32_t m0[4], m1[4];
        #pragma unroll
        for (int j = 0; j < 4; j++) { m0[j] = mrow0[t * 4 + j]; m1[j] = mrow1[t * 4 + j]; }

        // ---- QK half0 ----
        float sc[8][4];
        #pragma unroll
        for (int nt = 0; nt < 8; nt++)
            #pragma unroll
            for (int e = 0; e < 4; e++) sc[nt][e] = 0.f;
        #pragma unroll
        for (int ks = 0; ks < 4; ks++) {
            const int kb = ks * 16;
            uint32_t kf[8][2];
            #pragma unroll
            for (int g = 0; g < 4; g++) {
                uint32_t r0, r1, r2, r3;
                ldm_x4(r0, r1, r2, r3, smem_u32(&Kf[g * 16 + lr][kb + lc]));
                kf[2*g][0] = r0; kf[2*g+1][0] = r1; kf[2*g][1] = r2; kf[2*g+1][1] = r3;
            }
            #pragma unroll
            for (int nt = 0; nt < 8; nt++)
                mma_f16(sc[nt], qf[ks], kf[nt]);
        }

        // ---- pack half0 ----
        uint32_t pf0[4][4];
        #pragma unroll
        for (int nt = 0; nt < 8; nt++) {
            const uint32_t w0 = (nt < 4) ? m0[0] : m0[1];
            const uint32_t w1 = (nt < 4) ? m1[0] : m1[1];
            const int bp = (nt & 3) * 8 + tig * 2;
            pf0[nt >> 1][(nt & 1) * 2]     = h2exp2(packh2(sc[nt][0], sc[nt][1])) & mask2(w0, bp);
            pf0[nt >> 1][(nt & 1) * 2 + 1] = h2exp2(packh2(sc[nt][2], sc[nt][3])) & mask2(w1, bp);
        }

        // ---- QK half1 ----
        float sc1[8][4];
        #pragma unroll
        for (int nt = 0; nt < 8; nt++)
            #pragma unroll
            for (int e = 0; e < 4; e++) sc1[nt][e] = 0.f;
        #pragma unroll
        for (int ks = 0; ks < 4; ks++) {
            const int kb = ks * 16;
            uint32_t kf[8][2];
            #pragma unroll
            for (int g = 0; g < 4; g++) {
                uint32_t r0, r1, r2, r3;
                ldm_x4(r0, r1, r2, r3, smem_u32(&Kf[64 + g * 16 + lr][kb + lc]));
                kf[2*g][0] = r0; kf[2*g+1][0] = r1; kf[2*g][1] = r2; kf[2*g+1][1] = r3;
            }
            #pragma unroll
            for (int nt = 0; nt < 8; nt++)
                mma_f16(sc1[nt], qf[ks], kf[nt]);
        }

        // ---- PV half0 + rowsum ----
        #pragma unroll
        for (int kp = 0; kp < 4; kp++) {
            mma_f16(rsacc, pf0[kp], vones);
            const int krow = kp * 16 + vr;
            #pragma unroll
            for (int g = 0; g < 4; g++) {
                uint32_t vf[2][2];
                uint32_t r0, r1, r2, r3;
                ldm_x4_trans(r0, r1, r2, r3, smem_u32(&Vf[krow][g * 16 + vc]));
                vf[0][0] = r0; vf[1][0] = r1; vf[0][1] = r2; vf[1][1] = r3;
                mma_f16(oacc[2*g + 0], pf0[kp], vf[0]);
                mma_f16(oacc[2*g + 1], pf0[kp], vf[1]);
            }
        }

        // ---- pack half1 ----
        uint32_t pf1[4][4];
        #pragma unroll
        for (int nt = 0; nt < 8; nt++) {
            const uint32_t w0 = (nt < 4) ? m0[2] : m0[3];
            const uint32_t w1 = (nt < 4) ? m1[2] : m1[3];
            const int bp = (nt & 3) * 8 + tig * 2;
            pf1[nt >> 1][(nt & 1) * 2]     = h2exp2(packh2(sc1[nt][0], sc1[nt][1])) & mask2(w0, bp);
            pf1[nt >> 1][(nt & 1) * 2 + 1] = h2exp2(packh2(sc1[nt][2], sc1[nt][3])) & mask2(w1, bp);
        }

        // ---- PV half1 + rowsum ----
        #pragma unroll
        for (int kp = 0; kp < 4; kp++) {
            mma_f16(rsacc, pf1[kp], vones);
            const int krow = 64 + kp * 16 + vr;
            #pragma unroll
            for (int g = 0; g < 4; g++) {
                uint32_t vf[2][2];
                uint32_t r0, r1, r2, r3;
                ldm_x4_trans(r0, r1, r2, r3, smem_u32(&Vf[krow][g * 16 + vc]));
                vf[0][0] = r0; vf[1][0] = r1; vf[0][1] = r2; vf[1][1] = r3;
                mma_f16(oacc[2*g + 0], pf1[kp], vf[0]);
                mma_f16(oacc[2*g + 1], pf1[kp], vf[1]);
            }
        }
    }

    const float inv0 = 1.f / rsacc[0], inv1 = 1.f / rsacc[2];
    const size_t orow0 = (size_t)(b * SEQ + q0 + w * 16 + gid) * D_MODEL + h * HS;
    const size_t orow1 = orow0 + 8 * D_MODEL;
    #pragma unroll
    for (int nt = 0; nt < 8; nt++) {
        const int c = nt * 8 + tig * 2;
        *(uint32_t*)&of_g[orow0 + c] = packh2(oacc[nt][0] * inv0, oacc[nt][1] * inv0);
        *(uint32_t*)&of_g[orow1 + c] = packh2(oacc[nt][2] * inv1, oacc[nt][3] * inv1);
    }
}

// ---------------- launch ----------------
extern "C" void kernel_launch(void* const* d_in, const int* in_sizes, int n_in,
                              void* d_out, int out_size)
{
    const float* queries = (const float*)d_in[0];
    const float* keys    = (const float*)d_in[1];
    const float* values  = (const float*)d_in[2];
    const int*   mask    = (const int*)d_in[3];
    const float* Wq = (const float*)d_in[4];  const float* bq = (const float*)d_in[5];
    const float* Wk = (const float*)d_in[6];  const float* bk = (const float*)d_in[7];
    const float* Wv = (const float*)d_in[8];  const float* bv = (const float*)d_in[9];
    const float* Wy = (const float*)d_in[10]; const float* by = (const float*)d_in[11];
    const float* bq2 = (const float*)d_in[12];
    const float* bk2 = (const float*)d_in[13];
    const float* bv2 = (const float*)d_in[14];
    const float* by2 = (const float*)d_in[15];
    float* out = (float*)d_out;

    __half *xf, *wf, *qkvf, *of;
    uint32_t* mb;
    cudaGetSymbolAddress((void**)&xf, g_xf);
    cudaGetSymbolAddress((void**)&wf, g_wf);
    cudaGetSymbolAddress((void**)&qkvf, g_qkvf);
    cudaGetSymbolAddress((void**)&of, g_of);
    cudaGetSymbolAddress((void**)&mb, g_mbits);

    static int attr_set = 0;
    static cudaStream_t s2 = nullptr;
    static cudaEvent_t evFork = nullptr, evJoin = nullptr;
    if (!attr_set) {
        cudaFuncSetAttribute(qkv_gemm_kernel, cudaFuncAttributeMaxDynamicSharedMemorySize,
                             (int)sizeof(GS16));
        cudaFuncSetAttribute(y_gemm_kernel, cudaFuncAttributeMaxDynamicSharedMemorySize,
                             (int)sizeof(GS16));
        cudaFuncSetAttribute(attn_kernel, cudaFuncAttributeMaxDynamicSharedMemorySize,
                             AT_SMEM);
        if (cudaStreamCreateWithFlags(&s2, cudaStreamNonBlocking) != cudaSuccess) s2 = nullptr;
        if (s2) {
            if (cudaEventCreateWithFlags(&evFork, cudaEventDisableTiming) != cudaSuccess ||
                cudaEventCreateWithFlags(&evJoin, cudaEventDisableTiming) != cudaSuccess) {
                s2 = nullptr;
            }
        }
        attr_set = 1;
    }

    const int W4 = (int)(W_N / 4), A4 = (int)(ACT_N / 4);
    const bool fork = (s2 != nullptr);

    // ---- fork: persistent throttled mask bitpack coexists with QKV pipeline ----
    if (fork) {
        cudaEventRecord(evFork, 0);
        cudaStreamWaitEvent(s2, evFork, 0);
        maskbits_kernel<<<MB_CTAS, 256, 0, s2>>>(mask, mb);
        cudaEventRecord(evJoin, s2);
    } else {
        maskbits_kernel<<<MB_CTAS, 256>>>(mask, mb);
    }

    // ---- main stream: fp16 preconversion + fused QKV GEMM ----
    cvtw4_kernel<<<dim3(W4 / 256, 4), 256>>>(Wq, Wk, Wv, Wy, wf);
    cvta3_kernel<<<dim3(A4 / 256, 3), 256>>>(queries, keys, values, xf);

    dim3 qgrid(24, MROWS / 128);
    qkv_gemm_kernel<<<qgrid, 256, sizeof(GS16)>>>(xf, wf,
                                                  bq, bq2, bk, bk2, bv, bv2, qkvf);

    // ---- join before attention (needs mask bits) ----
    if (fork) cudaStreamWaitEvent(0, evJoin, 0);

    dim3 agrid(SEQ / 128, NH, BATCH);
    attn_kernel<<<agrid, 256, AT_SMEM>>>(qkvf, mb, of);

    dim3 ygrid(D_MODEL / 128, MROWS / 128);
    y_gemm_kernel<<<ygrid, 256, sizeof(GS16)>>>(of, wf + 3 * W_N, by, by2, out);
}